// round 1
// baseline (speedup 1.0000x reference)
#include <cuda_runtime.h>
#include <cuda_bf16.h>
#include <math.h>

// ---------------------------------------------------------------------------
// Problem constants
// ---------------------------------------------------------------------------
#define B_   8
#define S_   1024
#define D_   768
#define F_   3072
#define H_   12
#define DK_  64
#define M_   (B_ * S_)       // 8192 rows

// ---------------------------------------------------------------------------
// Scratch (device globals; no allocation allowed)
// ---------------------------------------------------------------------------
__device__ float g_q  [B_ * H_ * S_ * DK_];   // [B,H,S,dk]
__device__ float g_k  [B_ * H_ * S_ * DK_];
__device__ float g_v  [B_ * H_ * S_ * DK_];
__device__ float g_att[M_ * D_];              // attention output, [B,S,D]
__device__ float g_tmp[M_ * D_];              // residual branch scratch
__device__ float g_out1[M_ * D_];             // LN1 output
__device__ float g_ffh[M_ * F_];              // gelu(out1 @ W1 + b1)

// ---------------------------------------------------------------------------
// GELU (tanh approximation, matches reference)
// ---------------------------------------------------------------------------
__device__ __forceinline__ float gelu_t(float x) {
    const float c = 0.7978845608028654f;   // sqrt(2/pi)
    float t = tanhf(c * (x + 0.044715f * x * x * x));
    return 0.5f * x * (1.0f + t);
}

// ---------------------------------------------------------------------------
// SGEMM: C[M,N] = A[M,K] @ W[K,N] + bias, 128x128 tile, BK=8, 256 thr, 8x8/thr
// EPI: 0 = plain, 1 = gelu epilogue, 2 = store into [B,H,S,dk] head layout
// Requires M%128==0, N%128==0, K%8==0 (all true here).
// ---------------------------------------------------------------------------
template <int EPI>
__global__ void __launch_bounds__(256, 2)
sgemm128(const float* __restrict__ A, const float* __restrict__ W,
         const float* __restrict__ bias, float* __restrict__ C,
         int M, int N, int K)
{
    __shared__ float As[8][128];
    __shared__ float Bs[8][128];

    const int tid = threadIdx.x;
    const int m0 = blockIdx.y * 128;
    const int n0 = blockIdx.x * 128;

    const int tx = tid & 15;        // 0..15  -> col group
    const int ty = tid >> 4;        // 0..15  -> row group

    const int arow = tid >> 1;          // 0..127
    const int acol = (tid & 1) * 4;     // 0 or 4
    const int brow = tid >> 5;          // 0..7
    const int bcol = (tid & 31) * 4;    // 0..124

    float acc[8][8];
#pragma unroll
    for (int i = 0; i < 8; i++)
#pragma unroll
        for (int j = 0; j < 8; j++) acc[i][j] = 0.0f;

    for (int k0 = 0; k0 < K; k0 += 8) {
        float4 av = *(const float4*)&A[(size_t)(m0 + arow) * K + k0 + acol];
        float4 bv = *(const float4*)&W[(size_t)(k0 + brow) * N + n0 + bcol];

        __syncthreads();   // previous tile's compute done
        As[acol + 0][arow] = av.x;
        As[acol + 1][arow] = av.y;
        As[acol + 2][arow] = av.z;
        As[acol + 3][arow] = av.w;
        *(float4*)&Bs[brow][bcol] = bv;
        __syncthreads();

#pragma unroll
        for (int kk = 0; kk < 8; kk++) {
            float a[8], b[8];
            *(float4*)&a[0] = *(const float4*)&As[kk][ty * 8];
            *(float4*)&a[4] = *(const float4*)&As[kk][ty * 8 + 4];
            *(float4*)&b[0] = *(const float4*)&Bs[kk][tx * 8];
            *(float4*)&b[4] = *(const float4*)&Bs[kk][tx * 8 + 4];
#pragma unroll
            for (int i = 0; i < 8; i++)
#pragma unroll
                for (int j = 0; j < 8; j++)
                    acc[i][j] += a[i] * b[j];
        }
    }

    const int row0 = m0 + ty * 8;
    const int col0 = n0 + tx * 8;

    float bv[8];
#pragma unroll
    for (int j = 0; j < 8; j++) bv[j] = bias[col0 + j];

#pragma unroll
    for (int i = 0; i < 8; i++) {
        float out[8];
#pragma unroll
        for (int j = 0; j < 8; j++) {
            float v = acc[i][j] + bv[j];
            if (EPI == 1) v = gelu_t(v);
            out[j] = v;
        }
        const int row = row0 + i;
        if (EPI == 2) {
            // row = b*S + s ; col = h*64 + d -> [(b*H+h)*S + s]*64 + d
            const int bb = row >> 10;          // /1024
            const int ss = row & 1023;
            const int hh = col0 >> 6;          // col0..col0+7 stay in one head
            const int dd = col0 & 63;
            float* dst = &C[(size_t)((bb * H_ + hh) * S_ + ss) * DK_ + dd];
            *(float4*)&dst[0] = *(float4*)&out[0];
            *(float4*)&dst[4] = *(float4*)&out[4];
        } else {
            float* dst = &C[(size_t)row * N + col0];
            *(float4*)&dst[0] = *(float4*)&out[0];
            *(float4*)&dst[4] = *(float4*)&out[4];
        }
    }
}

// ---------------------------------------------------------------------------
// Flash attention (fp32): one block = (b, h, 128 queries); one thread = 1 row.
// Online softmax; K/V 64x64 tiles staged through shared memory.
// ---------------------------------------------------------------------------
__global__ void __launch_bounds__(128)
flash_attn_kernel(const float* __restrict__ Q, const float* __restrict__ K,
                  const float* __restrict__ V, const int* __restrict__ mask,
                  float* __restrict__ O)
{
    const int qt = blockIdx.x;   // query tile (0..7)
    const int h  = blockIdx.y;
    const int b  = blockIdx.z;
    const int t  = threadIdx.x;  // 0..127
    const int bh = b * H_ + h;

    __shared__ float Ks[64][64];
    __shared__ float Vs[64][64];
    __shared__ int   mk[64];

    const float* qp = Q + (size_t)(bh * S_ + qt * 128 + t) * DK_;
    float q[64];
#pragma unroll
    for (int i = 0; i < 64; i += 4) {
        float4 f = *(const float4*)(qp + i);
        q[i] = f.x; q[i + 1] = f.y; q[i + 2] = f.z; q[i + 3] = f.w;
    }

    float o[64];
#pragma unroll
    for (int i = 0; i < 64; i++) o[i] = 0.0f;
    float mx = -3.0e38f, l = 0.0f;

    const float* Kb = K + (size_t)bh * S_ * DK_;
    const float* Vb = V + (size_t)bh * S_ * DK_;

    for (int kt = 0; kt < 16; kt++) {
        __syncthreads();
#pragma unroll
        for (int i = 0; i < 8; i++) {
            int u = i * 128 + t;            // float4 unit 0..1023
            int r = u >> 4;
            int c = (u & 15) * 4;
            *(float4*)&Ks[r][c] = *(const float4*)&Kb[(size_t)(kt * 64 + r) * DK_ + c];
            *(float4*)&Vs[r][c] = *(const float4*)&Vb[(size_t)(kt * 64 + r) * DK_ + c];
        }
        if (t < 64) mk[t] = mask[b * S_ + kt * 64 + t];
        __syncthreads();

#pragma unroll 1
        for (int j = 0; j < 64; j++) {
            float s0 = 0.f, s1 = 0.f, s2 = 0.f, s3 = 0.f;
#pragma unroll
            for (int d = 0; d < 64; d += 16) {
                float4 k0 = *(const float4*)&Ks[j][d];
                float4 k1 = *(const float4*)&Ks[j][d + 4];
                float4 k2 = *(const float4*)&Ks[j][d + 8];
                float4 k3 = *(const float4*)&Ks[j][d + 12];
                s0 += q[d + 0] * k0.x + q[d + 1] * k0.y + q[d + 2] * k0.z + q[d + 3] * k0.w;
                s1 += q[d + 4] * k1.x + q[d + 5] * k1.y + q[d + 6] * k1.z + q[d + 7] * k1.w;
                s2 += q[d + 8] * k2.x + q[d + 9] * k2.y + q[d +10] * k2.z + q[d +11] * k2.w;
                s3 += q[d +12] * k3.x + q[d +13] * k3.y + q[d +14] * k3.z + q[d +15] * k3.w;
            }
            float s = ((s0 + s1) + (s2 + s3)) * 0.125f;   // / sqrt(64)
            if (mk[j] == 0) s = -1e9f;

            if (s > mx) {
                float sc = __expf(mx - s);
                mx = s;
                l *= sc;
#pragma unroll
                for (int d = 0; d < 64; d++) o[d] *= sc;
            }
            float p = __expf(s - mx);
            l += p;
#pragma unroll
            for (int d = 0; d < 64; d += 4) {
                float4 vv = *(const float4*)&Vs[j][d];
                o[d + 0] += p * vv.x;
                o[d + 1] += p * vv.y;
                o[d + 2] += p * vv.z;
                o[d + 3] += p * vv.w;
            }
        }
    }

    const float inv = 1.0f / l;
    float* op = O + (size_t)(b * S_ + qt * 128 + t) * D_ + h * DK_;
#pragma unroll
    for (int i = 0; i < 64; i += 4) {
        float4 f;
        f.x = o[i] * inv; f.y = o[i + 1] * inv;
        f.z = o[i + 2] * inv; f.w = o[i + 3] * inv;
        *(float4*)(op + i) = f;
    }
}

// ---------------------------------------------------------------------------
// Fused residual add + LayerNorm (torch-style: unbiased var, eps added to std)
// One block per row (768 cols), 256 threads, 3 values/thread.
// ---------------------------------------------------------------------------
__global__ void __launch_bounds__(256)
ln_residual_kernel(const float* __restrict__ X, const float* __restrict__ R,
                   const float* __restrict__ ga, const float* __restrict__ gb,
                   float* __restrict__ out)
{
    const int row = blockIdx.x;
    const int t   = threadIdx.x;
    const float* xr = X + (size_t)row * D_;
    const float* rr = R + (size_t)row * D_;

    float v[3];
#pragma unroll
    for (int i = 0; i < 3; i++) v[i] = xr[t + i * 256] + rr[t + i * 256];

    __shared__ float sbuf[8];

    // --- mean ---
    float s = v[0] + v[1] + v[2];
#pragma unroll
    for (int off = 16; off > 0; off >>= 1) s += __shfl_xor_sync(0xffffffffu, s, off);
    if ((t & 31) == 0) sbuf[t >> 5] = s;
    __syncthreads();
    float tot = 0.f;
#pragma unroll
    for (int i = 0; i < 8; i++) tot += sbuf[i];
    const float mean = tot * (1.0f / (float)D_);
    __syncthreads();

    // --- unbiased variance ---
    float d0 = v[0] - mean, d1 = v[1] - mean, d2 = v[2] - mean;
    float sq = d0 * d0 + d1 * d1 + d2 * d2;
#pragma unroll
    for (int off = 16; off > 0; off >>= 1) sq += __shfl_xor_sync(0xffffffffu, sq, off);
    if ((t & 31) == 0) sbuf[t >> 5] = sq;
    __syncthreads();
    float tot2 = 0.f;
#pragma unroll
    for (int i = 0; i < 8; i++) tot2 += sbuf[i];
    const float var = tot2 * (1.0f / (float)(D_ - 1));
    const float inv = 1.0f / (sqrtf(var) + 1e-6f);

    float* orow = out + (size_t)row * D_;
    orow[t      ] = ga[t      ] * d0 * inv + gb[t      ];
    orow[t + 256] = ga[t + 256] * d1 * inv + gb[t + 256];
    orow[t + 512] = ga[t + 512] * d2 * inv + gb[t + 512];
}

// ---------------------------------------------------------------------------
// Launch
// ---------------------------------------------------------------------------
extern "C" void kernel_launch(void* const* d_in, const int* in_sizes, int n_in,
                              void* d_out, int out_size)
{
    const float* x    = (const float*)d_in[0];
    const int*   mask = (const int*)  d_in[1];
    const float* Wq   = (const float*)d_in[2];
    const float* bq   = (const float*)d_in[3];
    const float* Wk   = (const float*)d_in[4];
    const float* bk   = (const float*)d_in[5];
    const float* Wv   = (const float*)d_in[6];
    const float* bv   = (const float*)d_in[7];
    const float* Wo   = (const float*)d_in[8];
    const float* bo   = (const float*)d_in[9];
    const float* W1   = (const float*)d_in[10];
    const float* b1   = (const float*)d_in[11];
    const float* W2   = (const float*)d_in[12];
    const float* b2   = (const float*)d_in[13];
    const float* ln1a = (const float*)d_in[14];
    const float* ln1b = (const float*)d_in[15];
    const float* ln2a = (const float*)d_in[16];
    const float* ln2b = (const float*)d_in[17];

    float *q, *k, *v, *att, *tmp, *out1, *ffh;
    cudaGetSymbolAddress((void**)&q,    g_q);
    cudaGetSymbolAddress((void**)&k,    g_k);
    cudaGetSymbolAddress((void**)&v,    g_v);
    cudaGetSymbolAddress((void**)&att,  g_att);
    cudaGetSymbolAddress((void**)&tmp,  g_tmp);
    cudaGetSymbolAddress((void**)&out1, g_out1);
    cudaGetSymbolAddress((void**)&ffh,  g_ffh);

    dim3 gProj(D_ / 128, M_ / 128);     // (6, 64)
    dim3 gFfn1(F_ / 128, M_ / 128);     // (24, 64)

    // QKV projections (write directly into [B,H,S,dk])
    sgemm128<2><<<gProj, 256>>>(x, Wq, bq, q, M_, D_, D_);
    sgemm128<2><<<gProj, 256>>>(x, Wk, bk, k, M_, D_, D_);
    sgemm128<2><<<gProj, 256>>>(x, Wv, bv, v, M_, D_, D_);

    // Attention
    dim3 gAttn(S_ / 128, H_, B_);       // (8, 12, 8)
    flash_attn_kernel<<<gAttn, 128>>>(q, k, v, mask, att);

    // Output projection
    sgemm128<0><<<gProj, 256>>>(att, Wo, bo, tmp, M_, D_, D_);

    // LN1(x + attn_out)
    ln_residual_kernel<<<M_, 256>>>(x, tmp, ln1a, ln1b, out1);

    // FFN: gelu(out1 @ W1 + b1) @ W2 + b2
    sgemm128<1><<<gFfn1, 256>>>(out1, W1, b1, ffh, M_, F_, D_);
    sgemm128<0><<<gProj, 256>>>(ffh, W2, b2, tmp, M_, D_, F_);

    // LN2(out1 + ffn) -> output
    ln_residual_kernel<<<M_, 256>>>(out1, tmp, ln2a, ln2b, (float*)d_out);
}

// round 3
// speedup vs baseline: 2.1024x; 2.1024x over previous
#include <cuda_runtime.h>
#include <cuda_bf16.h>
#include <math.h>
#include <stdint.h>

// ---------------------------------------------------------------------------
// Problem constants
// ---------------------------------------------------------------------------
#define B_   8
#define S_   1024
#define D_   768
#define F_   3072
#define H_   12
#define DK_  64
#define M_   (B_ * S_)       // 8192 rows

// ---------------------------------------------------------------------------
// Scratch (device globals; no allocation allowed)
// ---------------------------------------------------------------------------
__device__ float g_q  [B_ * H_ * S_ * DK_];
__device__ float g_k  [B_ * H_ * S_ * DK_];
__device__ float g_v  [B_ * H_ * S_ * DK_];
__device__ float g_att[M_ * D_];
__device__ float g_tmp[M_ * D_];
__device__ float g_out1[M_ * D_];
__device__ float g_ffh[M_ * F_];
// transposed weights, [N, K] K-major
__device__ float g_wqT[D_ * D_];
__device__ float g_wkT[D_ * D_];
__device__ float g_wvT[D_ * D_];
__device__ float g_woT[D_ * D_];
__device__ float g_w1T[F_ * D_];
__device__ float g_w2T[D_ * F_];

// ---------------------------------------------------------------------------
// Helpers
// ---------------------------------------------------------------------------
__device__ __forceinline__ uint32_t rna_tf32(float x) {
    uint32_t r;
    asm("cvt.rna.tf32.f32 %0, %1;" : "=r"(r) : "f"(x));
    return r;
}

// m16n8k8 TF32 MMA (sm_80+, works on sm_103 base target)
__device__ __forceinline__ void mma8(float* c,
                                     uint32_t a0, uint32_t a1, uint32_t a2, uint32_t a3,
                                     uint32_t b0, uint32_t b1)
{
    asm volatile(
        "mma.sync.aligned.m16n8k8.row.col.f32.tf32.tf32.f32 "
        "{%0,%1,%2,%3}, {%4,%5,%6,%7}, {%8,%9}, {%0,%1,%2,%3};"
        : "+f"(c[0]), "+f"(c[1]), "+f"(c[2]), "+f"(c[3])
        : "r"(a0), "r"(a1), "r"(a2), "r"(a3), "r"(b0), "r"(b1));
}

__device__ __forceinline__ float gelu_t(float x) {
    const float c = 0.7978845608028654f;
    float t = tanhf(c * (x + 0.044715f * x * x * x));
    return 0.5f * x * (1.0f + t);
}

// ---------------------------------------------------------------------------
// Weight transpose: W[K,N] -> Wt[N,K]
// ---------------------------------------------------------------------------
__global__ void __launch_bounds__(256)
transpose_k(const float* __restrict__ W, float* __restrict__ Wt, int K, int N)
{
    __shared__ float t[32][33];
    const int k0 = blockIdx.x * 32;
    const int n0 = blockIdx.y * 32;
    const int x = threadIdx.x;
    const int y = threadIdx.y;
#pragma unroll
    for (int i = 0; i < 32; i += 8)
        t[y + i][x] = W[(size_t)(k0 + y + i) * N + n0 + x];
    __syncthreads();
#pragma unroll
    for (int i = 0; i < 32; i += 8)
        Wt[(size_t)(n0 + y + i) * K + k0 + x] = t[x][y + i];
}

// ---------------------------------------------------------------------------
// TF32 mma.sync GEMM body.
//   C[M,N] = A[M,K] @ Bt[N,K]^T + bias
//   CTA 128x128, 256 threads (8 warps, 2x4), warp tile 64x32, BK=32.
//   Smem stride 36 words: fragment lds.32 conflict-free; sts.128 at floor.
//   EPI: 0 plain, 1 gelu, 2 head-split store to [B,H,S,dk]
// ---------------------------------------------------------------------------
#define SST 36   // smem row stride in words

template <int EPI>
__device__ __forceinline__ void gemm_body(
    const float* __restrict__ A, const float* __restrict__ Bt,
    const float* __restrict__ bias, float* __restrict__ C,
    int N, int K, int m0, int n0)
{
    __shared__ uint32_t As[128 * SST];
    __shared__ uint32_t Bs[128 * SST];

    const int tid  = threadIdx.x;
    const int warp = tid >> 5;
    const int lane = tid & 31;
    const int wm = (warp >> 2) * 64;     // warp m offset (0/64)
    const int wn = (warp & 3) * 32;      // warp n offset (0/32/64/96)
    const int lq = lane >> 2;            // 0..7
    const int tq = lane & 3;             // 0..3

    const int rr = tid >> 3;             // loader row 0..31
    const int cc = (tid & 7) * 4;        // loader col 0..28

    const float* Ap = A  + (size_t)(m0 + rr) * K + cc;
    const float* Bp = Bt + (size_t)(n0 + rr) * K + cc;

    float acc[4][4][4];
#pragma unroll
    for (int mi = 0; mi < 4; mi++)
#pragma unroll
        for (int ni = 0; ni < 4; ni++)
#pragma unroll
            for (int j = 0; j < 4; j++) acc[mi][ni][j] = 0.0f;

    float4 fa[4], fb[4];
#pragma unroll
    for (int i = 0; i < 4; i++) {
        fa[i] = *(const float4*)(Ap + (size_t)(i * 32) * K);
        fb[i] = *(const float4*)(Bp + (size_t)(i * 32) * K);
    }

    const int KIT = K >> 5;
    for (int it = 0; it < KIT; ++it) {
        __syncthreads();                       // prior iter done reading smem
#pragma unroll
        for (int i = 0; i < 4; i++) {
            uint4 ua;
            ua.x = rna_tf32(fa[i].x); ua.y = rna_tf32(fa[i].y);
            ua.z = rna_tf32(fa[i].z); ua.w = rna_tf32(fa[i].w);
            *(uint4*)&As[(rr + i * 32) * SST + cc] = ua;
            uint4 ub;
            ub.x = rna_tf32(fb[i].x); ub.y = rna_tf32(fb[i].y);
            ub.z = rna_tf32(fb[i].z); ub.w = rna_tf32(fb[i].w);
            *(uint4*)&Bs[(rr + i * 32) * SST + cc] = ub;
        }
        __syncthreads();

        if (it + 1 < KIT) {                    // prefetch next chunk
            const float* Ap2 = Ap + (it + 1) * 32;
            const float* Bp2 = Bp + (it + 1) * 32;
#pragma unroll
            for (int i = 0; i < 4; i++) {
                fa[i] = *(const float4*)(Ap2 + (size_t)(i * 32) * K);
                fb[i] = *(const float4*)(Bp2 + (size_t)(i * 32) * K);
            }
        }

#pragma unroll
        for (int s = 0; s < 4; ++s) {
            uint32_t bf[4][2];
#pragma unroll
            for (int ni = 0; ni < 4; ni++) {
                const int bb = (wn + ni * 8 + lq) * SST + s * 8 + tq;
                bf[ni][0] = Bs[bb];
                bf[ni][1] = Bs[bb + 4];
            }
#pragma unroll
            for (int mi = 0; mi < 4; mi++) {
                const int ab = (wm + mi * 16 + lq) * SST + s * 8 + tq;
                const uint32_t a0 = As[ab];
                const uint32_t a1 = As[ab + 8 * SST];
                const uint32_t a2 = As[ab + 4];
                const uint32_t a3 = As[ab + 8 * SST + 4];
#pragma unroll
                for (int ni = 0; ni < 4; ni++)
                    mma8(acc[mi][ni], a0, a1, a2, a3, bf[ni][0], bf[ni][1]);
            }
        }
    }

    // ---- epilogue ----
#pragma unroll
    for (int mi = 0; mi < 4; mi++) {
        const int r0 = m0 + wm + mi * 16 + lq;
#pragma unroll
        for (int ni = 0; ni < 4; ni++) {
            const int c0 = n0 + wn + ni * 8 + 2 * tq;
            const float bv0 = bias[c0];
            const float bv1 = bias[c0 + 1];
            float v00 = acc[mi][ni][0] + bv0;
            float v01 = acc[mi][ni][1] + bv1;
            float v10 = acc[mi][ni][2] + bv0;
            float v11 = acc[mi][ni][3] + bv1;
            if (EPI == 1) {
                v00 = gelu_t(v00); v01 = gelu_t(v01);
                v10 = gelu_t(v10); v11 = gelu_t(v11);
            }
            if (EPI == 2) {
                const int hh = c0 >> 6;
                const int dd = c0 & 63;
                {
                    const int bb = r0 >> 10, ss = r0 & 1023;
                    float2* dst = (float2*)&C[(size_t)((bb * H_ + hh) * S_ + ss) * DK_ + dd];
                    *dst = make_float2(v00, v01);
                }
                {
                    const int r1 = r0 + 8;
                    const int bb = r1 >> 10, ss = r1 & 1023;
                    float2* dst = (float2*)&C[(size_t)((bb * H_ + hh) * S_ + ss) * DK_ + dd];
                    *dst = make_float2(v10, v11);
                }
            } else {
                *(float2*)&C[(size_t)r0 * N + c0]       = make_float2(v00, v01);
                *(float2*)&C[(size_t)(r0 + 8) * N + c0] = make_float2(v10, v11);
            }
        }
    }
}

template <int EPI>
__global__ void __launch_bounds__(256)
mma_gemm(const float* __restrict__ A, const float* __restrict__ Bt,
         const float* __restrict__ bias, float* __restrict__ C,
         int N, int K)
{
    gemm_body<EPI>(A, Bt, bias, C, N, K, blockIdx.y * 128, blockIdx.x * 128);
}

// QKV fused: blockIdx.z picks the projection; EPI=2 head-split store.
__global__ void __launch_bounds__(256)
mma_gemm_qkv(const float* __restrict__ A,
             const float* __restrict__ wq, const float* __restrict__ wk,
             const float* __restrict__ wv,
             const float* __restrict__ bq, const float* __restrict__ bk,
             const float* __restrict__ bv,
             float* __restrict__ oq, float* __restrict__ ok, float* __restrict__ ov)
{
    const float* Bt;
    const float* bias;
    float* C;
    if (blockIdx.z == 0)      { Bt = wq; bias = bq; C = oq; }
    else if (blockIdx.z == 1) { Bt = wk; bias = bk; C = ok; }
    else                      { Bt = wv; bias = bv; C = ov; }
    gemm_body<2>(A, Bt, bias, C, D_, D_, blockIdx.y * 128, blockIdx.x * 128);
}

// ---------------------------------------------------------------------------
// Flash attention (fp32, unchanged from round 1)
// ---------------------------------------------------------------------------
__global__ void __launch_bounds__(128)
flash_attn_kernel(const float* __restrict__ Q, const float* __restrict__ K,
                  const float* __restrict__ V, const int* __restrict__ mask,
                  float* __restrict__ O)
{
    const int qt = blockIdx.x;
    const int h  = blockIdx.y;
    const int b  = blockIdx.z;
    const int t  = threadIdx.x;
    const int bh = b * H_ + h;

    __shared__ float Ks[64][64];
    __shared__ float Vs[64][64];
    __shared__ int   mk[64];

    const float* qp = Q + (size_t)(bh * S_ + qt * 128 + t) * DK_;
    float q[64];
#pragma unroll
    for (int i = 0; i < 64; i += 4) {
        float4 f = *(const float4*)(qp + i);
        q[i] = f.x; q[i + 1] = f.y; q[i + 2] = f.z; q[i + 3] = f.w;
    }

    float o[64];
#pragma unroll
    for (int i = 0; i < 64; i++) o[i] = 0.0f;
    float mx = -3.0e38f, l = 0.0f;

    const float* Kb = K + (size_t)bh * S_ * DK_;
    const float* Vb = V + (size_t)bh * S_ * DK_;

    for (int kt = 0; kt < 16; kt++) {
        __syncthreads();
#pragma unroll
        for (int i = 0; i < 8; i++) {
            int u = i * 128 + t;
            int r = u >> 4;
            int c = (u & 15) * 4;
            *(float4*)&Ks[r][c] = *(const float4*)&Kb[(size_t)(kt * 64 + r) * DK_ + c];
            *(float4*)&Vs[r][c] = *(const float4*)&Vb[(size_t)(kt * 64 + r) * DK_ + c];
        }
        if (t < 64) mk[t] = mask[b * S_ + kt * 64 + t];
        __syncthreads();

#pragma unroll 1
        for (int j = 0; j < 64; j++) {
            float s0 = 0.f, s1 = 0.f, s2 = 0.f, s3 = 0.f;
#pragma unroll
            for (int d = 0; d < 64; d += 16) {
                float4 k0 = *(const float4*)&Ks[j][d];
                float4 k1 = *(const float4*)&Ks[j][d + 4];
                float4 k2 = *(const float4*)&Ks[j][d + 8];
                float4 k3 = *(const float4*)&Ks[j][d + 12];
                s0 += q[d + 0] * k0.x + q[d + 1] * k0.y + q[d + 2] * k0.z + q[d + 3] * k0.w;
                s1 += q[d + 4] * k1.x + q[d + 5] * k1.y + q[d + 6] * k1.z + q[d + 7] * k1.w;
                s2 += q[d + 8] * k2.x + q[d + 9] * k2.y + q[d +10] * k2.z + q[d +11] * k2.w;
                s3 += q[d +12] * k3.x + q[d +13] * k3.y + q[d +14] * k3.z + q[d +15] * k3.w;
            }
            float s = ((s0 + s1) + (s2 + s3)) * 0.125f;
            if (mk[j] == 0) s = -1e9f;

            if (s > mx) {
                float sc = __expf(mx - s);
                mx = s;
                l *= sc;
#pragma unroll
                for (int d = 0; d < 64; d++) o[d] *= sc;
            }
            float p = __expf(s - mx);
            l += p;
#pragma unroll
            for (int d = 0; d < 64; d += 4) {
                float4 vv = *(const float4*)&Vs[j][d];
                o[d + 0] += p * vv.x;
                o[d + 1] += p * vv.y;
                o[d + 2] += p * vv.z;
                o[d + 3] += p * vv.w;
            }
        }
    }

    const float inv = 1.0f / l;
    float* op = O + (size_t)(b * S_ + qt * 128 + t) * D_ + h * DK_;
#pragma unroll
    for (int i = 0; i < 64; i += 4) {
        float4 f;
        f.x = o[i] * inv; f.y = o[i + 1] * inv;
        f.z = o[i + 2] * inv; f.w = o[i + 3] * inv;
        *(float4*)(op + i) = f;
    }
}

// ---------------------------------------------------------------------------
// Fused residual add + LayerNorm
// ---------------------------------------------------------------------------
__global__ void __launch_bounds__(256)
ln_residual_kernel(const float* __restrict__ X, const float* __restrict__ R,
                   const float* __restrict__ ga, const float* __restrict__ gb,
                   float* __restrict__ out)
{
    const int row = blockIdx.x;
    const int t   = threadIdx.x;
    const float* xr = X + (size_t)row * D_;
    const float* rr = R + (size_t)row * D_;

    float v[3];
#pragma unroll
    for (int i = 0; i < 3; i++) v[i] = xr[t + i * 256] + rr[t + i * 256];

    __shared__ float sbuf[8];

    float s = v[0] + v[1] + v[2];
#pragma unroll
    for (int off = 16; off > 0; off >>= 1) s += __shfl_xor_sync(0xffffffffu, s, off);
    if ((t & 31) == 0) sbuf[t >> 5] = s;
    __syncthreads();
    float tot = 0.f;
#pragma unroll
    for (int i = 0; i < 8; i++) tot += sbuf[i];
    const float mean = tot * (1.0f / (float)D_);
    __syncthreads();

    float d0 = v[0] - mean, d1 = v[1] - mean, d2 = v[2] - mean;
    float sq = d0 * d0 + d1 * d1 + d2 * d2;
#pragma unroll
    for (int off = 16; off > 0; off >>= 1) sq += __shfl_xor_sync(0xffffffffu, sq, off);
    if ((t & 31) == 0) sbuf[t >> 5] = sq;
    __syncthreads();
    float tot2 = 0.f;
#pragma unroll
    for (int i = 0; i < 8; i++) tot2 += sbuf[i];
    const float var = tot2 * (1.0f / (float)(D_ - 1));
    const float inv = 1.0f / (sqrtf(var) + 1e-6f);

    float* orow = out + (size_t)row * D_;
    orow[t      ] = ga[t      ] * d0 * inv + gb[t      ];
    orow[t + 256] = ga[t + 256] * d1 * inv + gb[t + 256];
    orow[t + 512] = ga[t + 512] * d2 * inv + gb[t + 512];
}

// ---------------------------------------------------------------------------
// Launch
// ---------------------------------------------------------------------------
extern "C" void kernel_launch(void* const* d_in, const int* in_sizes, int n_in,
                              void* d_out, int out_size)
{
    const float* x    = (const float*)d_in[0];
    const int*   mask = (const int*)  d_in[1];
    const float* Wq   = (const float*)d_in[2];
    const float* bq   = (const float*)d_in[3];
    const float* Wk   = (const float*)d_in[4];
    const float* bk   = (const float*)d_in[5];
    const float* Wv   = (const float*)d_in[6];
    const float* bv   = (const float*)d_in[7];
    const float* Wo   = (const float*)d_in[8];
    const float* bo   = (const float*)d_in[9];
    const float* W1   = (const float*)d_in[10];
    const float* b1   = (const float*)d_in[11];
    const float* W2   = (const float*)d_in[12];
    const float* b2   = (const float*)d_in[13];
    const float* ln1a = (const float*)d_in[14];
    const float* ln1b = (const float*)d_in[15];
    const float* ln2a = (const float*)d_in[16];
    const float* ln2b = (const float*)d_in[17];

    float *q, *k, *v, *att, *tmp, *out1, *ffh;
    float *wqT, *wkT, *wvT, *woT, *w1T, *w2T;
    cudaGetSymbolAddress((void**)&q,    g_q);
    cudaGetSymbolAddress((void**)&k,    g_k);
    cudaGetSymbolAddress((void**)&v,    g_v);
    cudaGetSymbolAddress((void**)&att,  g_att);
    cudaGetSymbolAddress((void**)&tmp,  g_tmp);
    cudaGetSymbolAddress((void**)&out1, g_out1);
    cudaGetSymbolAddress((void**)&ffh,  g_ffh);
    cudaGetSymbolAddress((void**)&wqT,  g_wqT);
    cudaGetSymbolAddress((void**)&wkT,  g_wkT);
    cudaGetSymbolAddress((void**)&wvT,  g_wvT);
    cudaGetSymbolAddress((void**)&woT,  g_woT);
    cudaGetSymbolAddress((void**)&w1T,  g_w1T);
    cudaGetSymbolAddress((void**)&w2T,  g_w2T);

    // Weight transposes ([K,N] -> [N,K])
    dim3 tb(32, 8);
    transpose_k<<<dim3(D_ / 32, D_ / 32), tb>>>(Wq, wqT, D_, D_);
    transpose_k<<<dim3(D_ / 32, D_ / 32), tb>>>(Wk, wkT, D_, D_);
    transpose_k<<<dim3(D_ / 32, D_ / 32), tb>>>(Wv, wvT, D_, D_);
    transpose_k<<<dim3(D_ / 32, D_ / 32), tb>>>(Wo, woT, D_, D_);
    transpose_k<<<dim3(D_ / 32, F_ / 32), tb>>>(W1, w1T, D_, F_);
    transpose_k<<<dim3(F_ / 32, D_ / 32), tb>>>(W2, w2T, F_, D_);

    dim3 gProj(D_ / 128, M_ / 128);          // (6, 64)
    dim3 gQkv (D_ / 128, M_ / 128, 3);       // (6, 64, 3)
    dim3 gFfn1(F_ / 128, M_ / 128);          // (24, 64)

    // QKV projections (fused launch) -> [B,H,S,dk]
    mma_gemm_qkv<<<gQkv, 256>>>(x, wqT, wkT, wvT, bq, bk, bv, q, k, v);

    // Attention
    dim3 gAttn(S_ / 128, H_, B_);
    flash_attn_kernel<<<gAttn, 128>>>(q, k, v, mask, att);

    // Output projection
    mma_gemm<0><<<gProj, 256>>>(att, woT, bo, tmp, D_, D_);

    // LN1(x + attn_out)
    ln_residual_kernel<<<M_, 256>>>(x, tmp, ln1a, ln1b, out1);

    // FFN
    mma_gemm<1><<<gFfn1, 256>>>(out1, w1T, b1, ffh, F_, D_);
    mma_gemm<0><<<gProj, 256>>>(ffh, w2T, b2, tmp, D_, F_);

    // LN2(out1 + ffn) -> output
    ln_residual_kernel<<<M_, 256>>>(out1, tmp, ln2a, ln2b, (float*)d_out);
}

// round 4
// speedup vs baseline: 3.4226x; 1.6279x over previous
#include <cuda_runtime.h>
#include <cuda_bf16.h>
#include <math.h>
#include <stdint.h>

// ---------------------------------------------------------------------------
// Problem constants
// ---------------------------------------------------------------------------
#define B_   8
#define S_   1024
#define D_   768
#define F_   3072
#define H_   12
#define DK_  64
#define M_   (B_ * S_)       // 8192 rows

// ---------------------------------------------------------------------------
// Scratch (device globals; no allocation allowed)
// ---------------------------------------------------------------------------
__device__ __nv_bfloat16 g_qb [B_ * H_ * S_ * DK_];   // [B,H,S,dk] bf16
__device__ __nv_bfloat16 g_kb [B_ * H_ * S_ * DK_];   // [B,H,S,dk] bf16
__device__ __nv_bfloat16 g_vtb[B_ * H_ * DK_ * S_];   // [B,H,dk,S] bf16 (V^T)
__device__ float g_att[M_ * D_];
__device__ float g_tmp[M_ * D_];
__device__ float g_out1[M_ * D_];
__device__ float g_ffh[M_ * F_];
// transposed weights, [N, K] K-major
__device__ float g_wqT[D_ * D_];
__device__ float g_wkT[D_ * D_];
__device__ float g_wvT[D_ * D_];
__device__ float g_woT[D_ * D_];
__device__ float g_w1T[F_ * D_];
__device__ float g_w2T[D_ * F_];

// ---------------------------------------------------------------------------
// Helpers
// ---------------------------------------------------------------------------
__device__ __forceinline__ uint32_t rna_tf32(float x) {
    uint32_t r;
    asm("cvt.rna.tf32.f32 %0, %1;" : "=r"(r) : "f"(x));
    return r;
}

// m16n8k8 TF32 MMA
__device__ __forceinline__ void mma8(float* c,
                                     uint32_t a0, uint32_t a1, uint32_t a2, uint32_t a3,
                                     uint32_t b0, uint32_t b1)
{
    asm volatile(
        "mma.sync.aligned.m16n8k8.row.col.f32.tf32.tf32.f32 "
        "{%0,%1,%2,%3}, {%4,%5,%6,%7}, {%8,%9}, {%0,%1,%2,%3};"
        : "+f"(c[0]), "+f"(c[1]), "+f"(c[2]), "+f"(c[3])
        : "r"(a0), "r"(a1), "r"(a2), "r"(a3), "r"(b0), "r"(b1));
}

// m16n8k16 BF16 MMA
__device__ __forceinline__ void mma16(float* c,
                                      uint32_t a0, uint32_t a1, uint32_t a2, uint32_t a3,
                                      uint32_t b0, uint32_t b1)
{
    asm volatile(
        "mma.sync.aligned.m16n8k16.row.col.f32.bf16.bf16.f32 "
        "{%0,%1,%2,%3}, {%4,%5,%6,%7}, {%8,%9}, {%0,%1,%2,%3};"
        : "+f"(c[0]), "+f"(c[1]), "+f"(c[2]), "+f"(c[3])
        : "r"(a0), "r"(a1), "r"(a2), "r"(a3), "r"(b0), "r"(b1));
}

// pack two fp32 -> bf16x2 (lo = first arg)
__device__ __forceinline__ uint32_t pack_bf16(float lo, float hi) {
    uint32_t r;
    asm("cvt.rn.bf16x2.f32 %0, %1, %2;" : "=r"(r) : "f"(hi), "f"(lo));
    return r;
}

__device__ __forceinline__ float gelu_t(float x) {
    const float c = 0.7978845608028654f;
    float t = tanhf(c * (x + 0.044715f * x * x * x));
    return 0.5f * x * (1.0f + t);
}

// ---------------------------------------------------------------------------
// Weight transpose: W[K,N] -> Wt[N,K]
// ---------------------------------------------------------------------------
__global__ void __launch_bounds__(256)
transpose_k(const float* __restrict__ W, float* __restrict__ Wt, int K, int N)
{
    __shared__ float t[32][33];
    const int k0 = blockIdx.x * 32;
    const int n0 = blockIdx.y * 32;
    const int x = threadIdx.x;
    const int y = threadIdx.y;
#pragma unroll
    for (int i = 0; i < 32; i += 8)
        t[y + i][x] = W[(size_t)(k0 + y + i) * N + n0 + x];
    __syncthreads();
#pragma unroll
    for (int i = 0; i < 32; i += 8)
        Wt[(size_t)(n0 + y + i) * K + k0 + x] = t[x][y + i];
}

// ---------------------------------------------------------------------------
// TF32 mma.sync GEMM body.
//   EPI: 0 plain fp32, 1 gelu fp32,
//        3 bf16 head-split [B,H,S,dk], 4 bf16 transposed head-split [B,H,dk,S]
// ---------------------------------------------------------------------------
#define SST 36   // smem row stride in words

template <int EPI>
__device__ __forceinline__ void gemm_body(
    const float* __restrict__ A, const float* __restrict__ Bt,
    const float* __restrict__ bias, float* __restrict__ C,
    int N, int K, int m0, int n0)
{
    __shared__ uint32_t As[128 * SST];
    __shared__ uint32_t Bs[128 * SST];

    const int tid  = threadIdx.x;
    const int warp = tid >> 5;
    const int lane = tid & 31;
    const int wm = (warp >> 2) * 64;
    const int wn = (warp & 3) * 32;
    const int lq = lane >> 2;
    const int tq = lane & 3;

    const int rr = tid >> 3;
    const int cc = (tid & 7) * 4;

    const float* Ap = A  + (size_t)(m0 + rr) * K + cc;
    const float* Bp = Bt + (size_t)(n0 + rr) * K + cc;

    float acc[4][4][4];
#pragma unroll
    for (int mi = 0; mi < 4; mi++)
#pragma unroll
        for (int ni = 0; ni < 4; ni++)
#pragma unroll
            for (int j = 0; j < 4; j++) acc[mi][ni][j] = 0.0f;

    float4 fa[4], fb[4];
#pragma unroll
    for (int i = 0; i < 4; i++) {
        fa[i] = *(const float4*)(Ap + (size_t)(i * 32) * K);
        fb[i] = *(const float4*)(Bp + (size_t)(i * 32) * K);
    }

    const int KIT = K >> 5;
    for (int it = 0; it < KIT; ++it) {
        __syncthreads();
#pragma unroll
        for (int i = 0; i < 4; i++) {
            uint4 ua;
            ua.x = rna_tf32(fa[i].x); ua.y = rna_tf32(fa[i].y);
            ua.z = rna_tf32(fa[i].z); ua.w = rna_tf32(fa[i].w);
            *(uint4*)&As[(rr + i * 32) * SST + cc] = ua;
            uint4 ub;
            ub.x = rna_tf32(fb[i].x); ub.y = rna_tf32(fb[i].y);
            ub.z = rna_tf32(fb[i].z); ub.w = rna_tf32(fb[i].w);
            *(uint4*)&Bs[(rr + i * 32) * SST + cc] = ub;
        }
        __syncthreads();

        if (it + 1 < KIT) {
            const float* Ap2 = Ap + (it + 1) * 32;
            const float* Bp2 = Bp + (it + 1) * 32;
#pragma unroll
            for (int i = 0; i < 4; i++) {
                fa[i] = *(const float4*)(Ap2 + (size_t)(i * 32) * K);
                fb[i] = *(const float4*)(Bp2 + (size_t)(i * 32) * K);
            }
        }

#pragma unroll
        for (int s = 0; s < 4; ++s) {
            uint32_t bf[4][2];
#pragma unroll
            for (int ni = 0; ni < 4; ni++) {
                const int bb = (wn + ni * 8 + lq) * SST + s * 8 + tq;
                bf[ni][0] = Bs[bb];
                bf[ni][1] = Bs[bb + 4];
            }
#pragma unroll
            for (int mi = 0; mi < 4; mi++) {
                const int ab = (wm + mi * 16 + lq) * SST + s * 8 + tq;
                const uint32_t a0 = As[ab];
                const uint32_t a1 = As[ab + 8 * SST];
                const uint32_t a2 = As[ab + 4];
                const uint32_t a3 = As[ab + 8 * SST + 4];
#pragma unroll
                for (int ni = 0; ni < 4; ni++)
                    mma8(acc[mi][ni], a0, a1, a2, a3, bf[ni][0], bf[ni][1]);
            }
        }
    }

    // ---- epilogue ----
#pragma unroll
    for (int mi = 0; mi < 4; mi++) {
        const int r0 = m0 + wm + mi * 16 + lq;
#pragma unroll
        for (int ni = 0; ni < 4; ni++) {
            const int c0 = n0 + wn + ni * 8 + 2 * tq;
            const float bv0 = bias[c0];
            const float bv1 = bias[c0 + 1];
            float v00 = acc[mi][ni][0] + bv0;
            float v01 = acc[mi][ni][1] + bv1;
            float v10 = acc[mi][ni][2] + bv0;
            float v11 = acc[mi][ni][3] + bv1;
            if (EPI == 1) {
                v00 = gelu_t(v00); v01 = gelu_t(v01);
                v10 = gelu_t(v10); v11 = gelu_t(v11);
            }
            if (EPI == 3) {
                // bf16 [B,H,S,dk]
                __nv_bfloat16* Cb = (__nv_bfloat16*)C;
                const int hh = c0 >> 6, dd = c0 & 63;
                {
                    const int bb = r0 >> 10, ss = r0 & 1023;
                    *(__nv_bfloat162*)&Cb[(size_t)((bb * H_ + hh) * S_ + ss) * DK_ + dd] =
                        __floats2bfloat162_rn(v00, v01);
                }
                {
                    const int r1 = r0 + 8;
                    const int bb = r1 >> 10, ss = r1 & 1023;
                    *(__nv_bfloat162*)&Cb[(size_t)((bb * H_ + hh) * S_ + ss) * DK_ + dd] =
                        __floats2bfloat162_rn(v10, v11);
                }
            } else if (EPI == 4) {
                // bf16 V^T [B,H,dk,S]
                __nv_bfloat16* Cb = (__nv_bfloat16*)C;
                const int hh = c0 >> 6, dd = c0 & 63;
                const int bb = r0 >> 10, ss = r0 & 1023;
                const size_t base = (size_t)((bb * H_ + hh) * DK_ + dd) * S_ + ss;
                Cb[base]           = __float2bfloat16_rn(v00);
                Cb[base + S_]      = __float2bfloat16_rn(v01);
                Cb[base + 8]       = __float2bfloat16_rn(v10);
                Cb[base + S_ + 8]  = __float2bfloat16_rn(v11);
            } else {
                *(float2*)&C[(size_t)r0 * N + c0]       = make_float2(v00, v01);
                *(float2*)&C[(size_t)(r0 + 8) * N + c0] = make_float2(v10, v11);
            }
        }
    }
}

template <int EPI>
__global__ void __launch_bounds__(256)
mma_gemm(const float* __restrict__ A, const float* __restrict__ Bt,
         const float* __restrict__ bias, float* __restrict__ C,
         int N, int K)
{
    gemm_body<EPI>(A, Bt, bias, C, N, K, blockIdx.y * 128, blockIdx.x * 128);
}

// Q/K projections fused (z = 0/1), bf16 head-split output
__global__ void __launch_bounds__(256)
mma_gemm_qk(const float* __restrict__ A,
            const float* __restrict__ wq, const float* __restrict__ wk,
            const float* __restrict__ bq, const float* __restrict__ bk,
            float* __restrict__ oq, float* __restrict__ ok)
{
    const float* Bt  = blockIdx.z == 0 ? wq : wk;
    const float* bia = blockIdx.z == 0 ? bq : bk;
    float* C         = blockIdx.z == 0 ? oq : ok;
    gemm_body<3>(A, Bt, bia, C, D_, D_, blockIdx.y * 128, blockIdx.x * 128);
}

// ---------------------------------------------------------------------------
// BF16 tensor-core flash attention.
// Block = 128 threads (4 warps), each warp owns 16 query rows -> 64 q/CTA.
// Grid = (S/64, H, B). K tiles of 128 keys. V is pre-transposed [B,H,dk,S].
// ---------------------------------------------------------------------------
__global__ void __launch_bounds__(128)
flash_attn_bf16(const __nv_bfloat16* __restrict__ Q,
                const __nv_bfloat16* __restrict__ K,
                const __nv_bfloat16* __restrict__ Vt,
                const int* __restrict__ mask,
                float* __restrict__ O)
{
    const int qt = blockIdx.x;    // 0..15
    const int h  = blockIdx.y;
    const int b  = blockIdx.z;
    const int tid  = threadIdx.x;
    const int warp = tid >> 5;
    const int lane = tid & 31;
    const int lq = lane >> 2;
    const int tq = lane & 3;
    const int bh = b * H_ + h;

    __shared__ __nv_bfloat16 Ks[128 * 72];   // K tile (also Q staging)
    __shared__ __nv_bfloat16 Vs[64 * 136];   // V^T tile
    __shared__ int mk[128];

    // ---- stage Q (64x64) into Ks, load A fragments ----
    {
        const __nv_bfloat16* Qb = Q + (size_t)(bh * S_ + qt * 64) * DK_;
        const int r = tid >> 1, hf = tid & 1;
        const uint4* src = (const uint4*)(Qb + r * DK_ + hf * 32);
        uint4* dst = (uint4*)&Ks[r * 72 + hf * 32];
#pragma unroll
        for (int i = 0; i < 4; i++) dst[i] = src[i];
    }
    __syncthreads();
    uint32_t qa[4][4];
    {
        const int r0 = warp * 16 + lq;
#pragma unroll
        for (int ks = 0; ks < 4; ks++) {
            qa[ks][0] = *(const uint32_t*)&Ks[(r0    ) * 72 + ks * 16 + 2 * tq];
            qa[ks][1] = *(const uint32_t*)&Ks[(r0 + 8) * 72 + ks * 16 + 2 * tq];
            qa[ks][2] = *(const uint32_t*)&Ks[(r0    ) * 72 + ks * 16 + 8 + 2 * tq];
            qa[ks][3] = *(const uint32_t*)&Ks[(r0 + 8) * 72 + ks * 16 + 8 + 2 * tq];
        }
    }
    __syncthreads();

    float o[8][4];
#pragma unroll
    for (int t = 0; t < 8; t++)
#pragma unroll
        for (int j = 0; j < 4; j++) o[t][j] = 0.0f;
    float m0 = -1e30f, m1 = -1e30f, l0 = 0.0f, l1 = 0.0f;

    const __nv_bfloat16* Kb = K  + (size_t)bh * S_ * DK_;
    const __nv_bfloat16* Vb = Vt + (size_t)bh * DK_ * S_;

    for (int kt = 0; kt < 8; kt++) {
        // load K tile 128x64 (1 row per thread)
        {
            const uint4* src = (const uint4*)(Kb + (size_t)(kt * 128 + tid) * DK_);
            uint4* dst = (uint4*)&Ks[tid * 72];
#pragma unroll
            for (int i = 0; i < 8; i++) dst[i] = src[i];
        }
        // load V^T tile 64x128 (half row per thread)
        {
            const int r = tid >> 1, hf = tid & 1;
            const uint4* src = (const uint4*)(Vb + (size_t)r * S_ + kt * 128 + hf * 64);
            uint4* dst = (uint4*)&Vs[r * 136 + hf * 64];
#pragma unroll
            for (int i = 0; i < 8; i++) dst[i] = src[i];
        }
        mk[tid] = mask[b * S_ + kt * 128 + tid];
        __syncthreads();

        // ---- scores: QK^T (16 n-tiles of 8 keys) ----
        float s[16][4];
#pragma unroll
        for (int nt = 0; nt < 16; nt++) {
            s[nt][0] = s[nt][1] = s[nt][2] = s[nt][3] = 0.0f;
#pragma unroll
            for (int ks = 0; ks < 4; ks++) {
                const uint32_t b0 = *(const uint32_t*)&Ks[(nt * 8 + lq) * 72 + ks * 16 + 2 * tq];
                const uint32_t b1 = *(const uint32_t*)&Ks[(nt * 8 + lq) * 72 + ks * 16 + 8 + 2 * tq];
                mma16(s[nt], qa[ks][0], qa[ks][1], qa[ks][2], qa[ks][3], b0, b1);
            }
        }

        // ---- scale + mask + online softmax ----
        float mx0 = -1e30f, mx1 = -1e30f;
#pragma unroll
        for (int nt = 0; nt < 16; nt++) {
            const int c = nt * 8 + 2 * tq;
            const bool k0 = mk[c] != 0, k1 = mk[c + 1] != 0;
            s[nt][0] = k0 ? s[nt][0] * 0.125f : -1e9f;
            s[nt][1] = k1 ? s[nt][1] * 0.125f : -1e9f;
            s[nt][2] = k0 ? s[nt][2] * 0.125f : -1e9f;
            s[nt][3] = k1 ? s[nt][3] * 0.125f : -1e9f;
            mx0 = fmaxf(mx0, fmaxf(s[nt][0], s[nt][1]));
            mx1 = fmaxf(mx1, fmaxf(s[nt][2], s[nt][3]));
        }
        mx0 = fmaxf(mx0, __shfl_xor_sync(0xffffffffu, mx0, 1));
        mx0 = fmaxf(mx0, __shfl_xor_sync(0xffffffffu, mx0, 2));
        mx1 = fmaxf(mx1, __shfl_xor_sync(0xffffffffu, mx1, 1));
        mx1 = fmaxf(mx1, __shfl_xor_sync(0xffffffffu, mx1, 2));

        const float nm0 = fmaxf(m0, mx0);
        const float nm1 = fmaxf(m1, mx1);
        const float al0 = __expf(m0 - nm0);
        const float al1 = __expf(m1 - nm1);
        m0 = nm0; m1 = nm1;

        float ps0 = 0.0f, ps1 = 0.0f;
#pragma unroll
        for (int nt = 0; nt < 16; nt++) {
            s[nt][0] = __expf(s[nt][0] - m0);
            s[nt][1] = __expf(s[nt][1] - m0);
            s[nt][2] = __expf(s[nt][2] - m1);
            s[nt][3] = __expf(s[nt][3] - m1);
            ps0 += s[nt][0] + s[nt][1];
            ps1 += s[nt][2] + s[nt][3];
        }
        ps0 += __shfl_xor_sync(0xffffffffu, ps0, 1);
        ps0 += __shfl_xor_sync(0xffffffffu, ps0, 2);
        ps1 += __shfl_xor_sync(0xffffffffu, ps1, 1);
        ps1 += __shfl_xor_sync(0xffffffffu, ps1, 2);
        l0 = l0 * al0 + ps0;
        l1 = l1 * al1 + ps1;

#pragma unroll
        for (int t = 0; t < 8; t++) {
            o[t][0] *= al0; o[t][1] *= al0;
            o[t][2] *= al1; o[t][3] *= al1;
        }

        // ---- PV: P(16x128) @ V(128x64), P frags straight from score accs ----
#pragma unroll
        for (int kc = 0; kc < 8; kc++) {
            const uint32_t a0 = pack_bf16(s[2 * kc][0],     s[2 * kc][1]);
            const uint32_t a1 = pack_bf16(s[2 * kc][2],     s[2 * kc][3]);
            const uint32_t a2 = pack_bf16(s[2 * kc + 1][0], s[2 * kc + 1][1]);
            const uint32_t a3 = pack_bf16(s[2 * kc + 1][2], s[2 * kc + 1][3]);
#pragma unroll
            for (int t = 0; t < 8; t++) {
                const uint32_t b0 = *(const uint32_t*)&Vs[(t * 8 + lq) * 136 + kc * 16 + 2 * tq];
                const uint32_t b1 = *(const uint32_t*)&Vs[(t * 8 + lq) * 136 + kc * 16 + 8 + 2 * tq];
                mma16(o[t], a0, a1, a2, a3, b0, b1);
            }
        }
        __syncthreads();
    }

    // ---- write out (fp32, [B,S,D] with head offset) ----
    const float i0 = 1.0f / l0;
    const float i1 = 1.0f / l1;
    const int qr = qt * 64 + warp * 16 + lq;
    float* O0 = O + (size_t)(b * S_ + qr) * D_ + h * DK_;
    float* O1 = O0 + (size_t)8 * D_;
#pragma unroll
    for (int t = 0; t < 8; t++) {
        *(float2*)(O0 + t * 8 + 2 * tq) = make_float2(o[t][0] * i0, o[t][1] * i0);
        *(float2*)(O1 + t * 8 + 2 * tq) = make_float2(o[t][2] * i1, o[t][3] * i1);
    }
}

// ---------------------------------------------------------------------------
// Fused residual add + LayerNorm
// ---------------------------------------------------------------------------
__global__ void __launch_bounds__(256)
ln_residual_kernel(const float* __restrict__ X, const float* __restrict__ R,
                   const float* __restrict__ ga, const float* __restrict__ gb,
                   float* __restrict__ out)
{
    const int row = blockIdx.x;
    const int t   = threadIdx.x;
    const float* xr = X + (size_t)row * D_;
    const float* rr = R + (size_t)row * D_;

    float v[3];
#pragma unroll
    for (int i = 0; i < 3; i++) v[i] = xr[t + i * 256] + rr[t + i * 256];

    __shared__ float sbuf[8];

    float s = v[0] + v[1] + v[2];
#pragma unroll
    for (int off = 16; off > 0; off >>= 1) s += __shfl_xor_sync(0xffffffffu, s, off);
    if ((t & 31) == 0) sbuf[t >> 5] = s;
    __syncthreads();
    float tot = 0.f;
#pragma unroll
    for (int i = 0; i < 8; i++) tot += sbuf[i];
    const float mean = tot * (1.0f / (float)D_);
    __syncthreads();

    float d0 = v[0] - mean, d1 = v[1] - mean, d2 = v[2] - mean;
    float sq = d0 * d0 + d1 * d1 + d2 * d2;
#pragma unroll
    for (int off = 16; off > 0; off >>= 1) sq += __shfl_xor_sync(0xffffffffu, sq, off);
    if ((t & 31) == 0) sbuf[t >> 5] = sq;
    __syncthreads();
    float tot2 = 0.f;
#pragma unroll
    for (int i = 0; i < 8; i++) tot2 += sbuf[i];
    const float var = tot2 * (1.0f / (float)(D_ - 1));
    const float inv = 1.0f / (sqrtf(var) + 1e-6f);

    float* orow = out + (size_t)row * D_;
    orow[t      ] = ga[t      ] * d0 * inv + gb[t      ];
    orow[t + 256] = ga[t + 256] * d1 * inv + gb[t + 256];
    orow[t + 512] = ga[t + 512] * d2 * inv + gb[t + 512];
}

// ---------------------------------------------------------------------------
// Launch
// ---------------------------------------------------------------------------
extern "C" void kernel_launch(void* const* d_in, const int* in_sizes, int n_in,
                              void* d_out, int out_size)
{
    const float* x    = (const float*)d_in[0];
    const int*   mask = (const int*)  d_in[1];
    const float* Wq   = (const float*)d_in[2];
    const float* bq   = (const float*)d_in[3];
    const float* Wk   = (const float*)d_in[4];
    const float* bk   = (const float*)d_in[5];
    const float* Wv   = (const float*)d_in[6];
    const float* bv   = (const float*)d_in[7];
    const float* Wo   = (const float*)d_in[8];
    const float* bo   = (const float*)d_in[9];
    const float* W1   = (const float*)d_in[10];
    const float* b1   = (const float*)d_in[11];
    const float* W2   = (const float*)d_in[12];
    const float* b2   = (const float*)d_in[13];
    const float* ln1a = (const float*)d_in[14];
    const float* ln1b = (const float*)d_in[15];
    const float* ln2a = (const float*)d_in[16];
    const float* ln2b = (const float*)d_in[17];

    __nv_bfloat16 *qb, *kb, *vtb;
    float *att, *tmp, *out1, *ffh;
    float *wqT, *wkT, *wvT, *woT, *w1T, *w2T;
    cudaGetSymbolAddress((void**)&qb,   g_qb);
    cudaGetSymbolAddress((void**)&kb,   g_kb);
    cudaGetSymbolAddress((void**)&vtb,  g_vtb);
    cudaGetSymbolAddress((void**)&att,  g_att);
    cudaGetSymbolAddress((void**)&tmp,  g_tmp);
    cudaGetSymbolAddress((void**)&out1, g_out1);
    cudaGetSymbolAddress((void**)&ffh,  g_ffh);
    cudaGetSymbolAddress((void**)&wqT,  g_wqT);
    cudaGetSymbolAddress((void**)&wkT,  g_wkT);
    cudaGetSymbolAddress((void**)&wvT,  g_wvT);
    cudaGetSymbolAddress((void**)&woT,  g_woT);
    cudaGetSymbolAddress((void**)&w1T,  g_w1T);
    cudaGetSymbolAddress((void**)&w2T,  g_w2T);

    // Weight transposes ([K,N] -> [N,K])
    dim3 tb(32, 8);
    transpose_k<<<dim3(D_ / 32, D_ / 32), tb>>>(Wq, wqT, D_, D_);
    transpose_k<<<dim3(D_ / 32, D_ / 32), tb>>>(Wk, wkT, D_, D_);
    transpose_k<<<dim3(D_ / 32, D_ / 32), tb>>>(Wv, wvT, D_, D_);
    transpose_k<<<dim3(D_ / 32, D_ / 32), tb>>>(Wo, woT, D_, D_);
    transpose_k<<<dim3(D_ / 32, F_ / 32), tb>>>(W1, w1T, D_, F_);
    transpose_k<<<dim3(F_ / 32, D_ / 32), tb>>>(W2, w2T, F_, D_);

    dim3 gProj(D_ / 128, M_ / 128);          // (6, 64)
    dim3 gQk  (D_ / 128, M_ / 128, 2);       // (6, 64, 2)
    dim3 gFfn1(F_ / 128, M_ / 128);          // (24, 64)

    // Q,K projections (bf16 head-split) + V projection (bf16 transposed)
    mma_gemm_qk<<<gQk, 256>>>(x, wqT, wkT, bq, bk, (float*)qb, (float*)kb);
    mma_gemm<4><<<gProj, 256>>>(x, wvT, bv, (float*)vtb, D_, D_);

    // Attention (bf16 tensor cores)
    dim3 gAttn(S_ / 64, H_, B_);             // (16, 12, 8)
    flash_attn_bf16<<<gAttn, 128>>>(qb, kb, vtb, mask, att);

    // Output projection
    mma_gemm<0><<<gProj, 256>>>(att, woT, bo, tmp, D_, D_);

    // LN1(x + attn_out)
    ln_residual_kernel<<<M_, 256>>>(x, tmp, ln1a, ln1b, out1);

    // FFN
    mma_gemm<1><<<gFfn1, 256>>>(out1, w1T, b1, ffh, F_, D_);
    mma_gemm<0><<<gProj, 256>>>(ffh, w2T, b2, tmp, D_, F_);

    // LN2(out1 + ffn) -> output
    ln_residual_kernel<<<M_, 256>>>(out1, tmp, ln2a, ln2b, (float*)d_out);
}

// round 5
// speedup vs baseline: 3.8901x; 1.1366x over previous
#include <cuda_runtime.h>
#include <cuda_bf16.h>
#include <math.h>
#include <stdint.h>

// ---------------------------------------------------------------------------
// Problem constants
// ---------------------------------------------------------------------------
#define B_   8
#define S_   1024
#define D_   768
#define F_   3072
#define H_   12
#define DK_  64
#define M_   (B_ * S_)       // 8192 rows

// ---------------------------------------------------------------------------
// Scratch (device globals; no allocation allowed)
// ---------------------------------------------------------------------------
__device__ __align__(16) __nv_bfloat16 g_qb [B_ * H_ * S_ * DK_];   // [B,H,S,dk]
__device__ __align__(16) __nv_bfloat16 g_kb [B_ * H_ * S_ * DK_];   // [B,H,S,dk]
__device__ __align__(16) __nv_bfloat16 g_vtb[B_ * H_ * DK_ * S_];   // [B,H,dk,S]
__device__ __align__(16) float g_xr  [M_ * D_];    // x rounded to tf32
__device__ __align__(16) float g_att [M_ * D_];    // attention out (tf32)
__device__ __align__(16) float g_tmp [M_ * D_];    // fp32 scratch
__device__ __align__(16) float g_out1[M_ * D_];    // LN1 out fp32
__device__ __align__(16) float g_o1r [M_ * D_];    // LN1 out tf32
__device__ __align__(16) float g_ffh [M_ * F_];    // gelu out (tf32)
// transposed weights, [N, K] K-major, tf32-rounded
__device__ __align__(16) float g_wqT[D_ * D_];
__device__ __align__(16) float g_wkT[D_ * D_];
__device__ __align__(16) float g_wvT[D_ * D_];
__device__ __align__(16) float g_woT[D_ * D_];
__device__ __align__(16) float g_w1T[F_ * D_];
__device__ __align__(16) float g_w2T[D_ * F_];

// ---------------------------------------------------------------------------
// Helpers
// ---------------------------------------------------------------------------
__device__ __forceinline__ uint32_t smem_u32(const void* p) {
    uint32_t a;
    asm("{ .reg .u64 t; cvta.to.shared.u64 t, %1; cvt.u32.u64 %0, t; }"
        : "=r"(a) : "l"(p));
    return a;
}
__device__ __forceinline__ uint32_t rna_tf32(float x) {
    uint32_t r;
    asm("cvt.rna.tf32.f32 %0, %1;" : "=r"(r) : "f"(x));
    return r;
}
__device__ __forceinline__ float rf(float x) {          // tf32-rounded fp32
    return __uint_as_float(rna_tf32(x));
}

__device__ __forceinline__ void cp16(uint32_t dst, const void* src) {
    asm volatile("cp.async.cg.shared.global [%0], [%1], 16;"
                 :: "r"(dst), "l"(src) : "memory");
}
#define CP_COMMIT asm volatile("cp.async.commit_group;" ::: "memory")
#define CP_WAIT2  asm volatile("cp.async.wait_group 2;" ::: "memory")

// m16n8k8 TF32 MMA
__device__ __forceinline__ void mma8(float* c,
                                     uint32_t a0, uint32_t a1, uint32_t a2, uint32_t a3,
                                     uint32_t b0, uint32_t b1)
{
    asm volatile(
        "mma.sync.aligned.m16n8k8.row.col.f32.tf32.tf32.f32 "
        "{%0,%1,%2,%3}, {%4,%5,%6,%7}, {%8,%9}, {%0,%1,%2,%3};"
        : "+f"(c[0]), "+f"(c[1]), "+f"(c[2]), "+f"(c[3])
        : "r"(a0), "r"(a1), "r"(a2), "r"(a3), "r"(b0), "r"(b1));
}

// m16n8k16 BF16 MMA
__device__ __forceinline__ void mma16(float* c,
                                      uint32_t a0, uint32_t a1, uint32_t a2, uint32_t a3,
                                      uint32_t b0, uint32_t b1)
{
    asm volatile(
        "mma.sync.aligned.m16n8k16.row.col.f32.bf16.bf16.f32 "
        "{%0,%1,%2,%3}, {%4,%5,%6,%7}, {%8,%9}, {%0,%1,%2,%3};"
        : "+f"(c[0]), "+f"(c[1]), "+f"(c[2]), "+f"(c[3])
        : "r"(a0), "r"(a1), "r"(a2), "r"(a3), "r"(b0), "r"(b1));
}

__device__ __forceinline__ uint32_t pack_bf16(float lo, float hi) {
    uint32_t r;
    asm("cvt.rn.bf16x2.f32 %0, %1, %2;" : "=r"(r) : "f"(hi), "f"(lo));
    return r;
}

__device__ __forceinline__ float gelu_t(float x) {
    const float c = 0.7978845608028654f;
    float t = tanhf(c * (x + 0.044715f * x * x * x));
    return 0.5f * x * (1.0f + t);
}

// ---------------------------------------------------------------------------
// x -> tf32-rounded copy
// ---------------------------------------------------------------------------
__global__ void __launch_bounds__(256)
round_x_kernel(const float4* __restrict__ in, float4* __restrict__ out)
{
    const int i = blockIdx.x * 256 + threadIdx.x;
    float4 v = in[i];
    v.x = rf(v.x); v.y = rf(v.y); v.z = rf(v.z); v.w = rf(v.w);
    out[i] = v;
}

// ---------------------------------------------------------------------------
// Weight transpose W[K,N] -> Wt[N,K], tf32-rounded output
// ---------------------------------------------------------------------------
__device__ __forceinline__ void transpose_body(
    const float* __restrict__ W, float* __restrict__ Wt, int K, int N)
{
    __shared__ float t[32][33];
    const int k0 = blockIdx.x * 32;
    const int n0 = blockIdx.y * 32;
    const int x = threadIdx.x;
    const int y = threadIdx.y;
#pragma unroll
    for (int i = 0; i < 32; i += 8)
        t[y + i][x] = W[(size_t)(k0 + y + i) * N + n0 + x];
    __syncthreads();
#pragma unroll
    for (int i = 0; i < 32; i += 8)
        Wt[(size_t)(n0 + y + i) * K + k0 + x] = rf(t[x][y + i]);
}

__global__ void __launch_bounds__(256)
transpose_k(const float* __restrict__ W, float* __restrict__ Wt, int K, int N)
{
    transpose_body(W, Wt, K, N);
}

__global__ void __launch_bounds__(256)
transpose_qkvo(const float* __restrict__ Wq, const float* __restrict__ Wk,
               const float* __restrict__ Wv, const float* __restrict__ Wo,
               float* __restrict__ oq, float* __restrict__ ok,
               float* __restrict__ ov, float* __restrict__ oo)
{
    const float* W; float* Wt;
    if (blockIdx.z == 0)      { W = Wq; Wt = oq; }
    else if (blockIdx.z == 1) { W = Wk; Wt = ok; }
    else if (blockIdx.z == 2) { W = Wv; Wt = ov; }
    else                      { W = Wo; Wt = oo; }
    transpose_body(W, Wt, D_, D_);
}

// ---------------------------------------------------------------------------
// TF32 mma.sync GEMM, cp.async 3-stage pipeline.
//   C[M,N] = A[M,K] @ Bt[N,K]^T + bias
//   CTA 128x128, 128 threads (4 warps, 2x2), warp tile 64x64, BK=32.
//   A and Bt MUST be pre-rounded to tf32 (fp32 storage, low 13 bits zero).
//   EPI: 0 plain fp32, 1 gelu (tf32-rounded out),
//        3 bf16 head-split [B,H,S,dk], 4 bf16 transposed head-split [B,H,dk,S]
// ---------------------------------------------------------------------------
#define SST  36                      // smem row stride in words
#define STGW (128 * SST)             // words per tile stage
#define STGB (STGW * 4)              // bytes per tile stage
#define GEMM_SMEM (6 * STGB)         // 110592 bytes (3 stages x (A,B))

template <int EPI>
__device__ __forceinline__ void gemm_body(
    const float* __restrict__ A, const float* __restrict__ Bt,
    const float* __restrict__ bias, float* __restrict__ C,
    int N, int K, int m0, int n0)
{
    extern __shared__ uint32_t sm[];
    const uint32_t sbase = smem_u32(sm);

    const int tid  = threadIdx.x;
    const int warp = tid >> 5;
    const int lane = tid & 31;
    const int wm = (warp >> 1) * 64;     // 0/64
    const int wn = (warp & 1) * 64;      // 0/64
    const int lq = lane >> 2;
    const int tq = lane & 3;

    const int rr = tid >> 3;             // 0..15
    const int cc = (tid & 7) * 4;        // 0..28

    const float* Ap = A  + (size_t)(m0 + rr) * K + cc;
    const float* Bp = Bt + (size_t)(n0 + rr) * K + cc;
    const uint32_t dA = sbase + (uint32_t)(rr * SST + cc) * 4;
    const uint32_t dB = dA + 3 * STGB;

    const int KIT = K >> 5;

    float acc[4][8][4];
#pragma unroll
    for (int mi = 0; mi < 4; mi++)
#pragma unroll
        for (int ni = 0; ni < 8; ni++)
#pragma unroll
            for (int j = 0; j < 4; j++) acc[mi][ni][j] = 0.0f;

    // pipeline issue of chunk `it` into stage it%3
    auto issue = [&](int it) {
        if (it < KIT) {
            const float* a = Ap + it * 32;
            const float* b = Bp + it * 32;
            const uint32_t off = (uint32_t)(it % 3) * STGB;
#pragma unroll
            for (int i = 0; i < 8; i++) {
                cp16(dA + off + (uint32_t)(i * 16 * SST) * 4, a + (size_t)(i * 16) * K);
                cp16(dB + off + (uint32_t)(i * 16 * SST) * 4, b + (size_t)(i * 16) * K);
            }
        }
        CP_COMMIT;
    };

    issue(0); issue(1); issue(2);

    for (int it = 0; it < KIT; ++it) {
        CP_WAIT2;
        __syncthreads();
        const uint32_t* As = sm + (it % 3) * STGW;
        const uint32_t* Bs = As + 3 * STGW;

#pragma unroll
        for (int s = 0; s < 4; ++s) {
            uint32_t bf[8][2];
#pragma unroll
            for (int ni = 0; ni < 8; ni++) {
                const int bb = (wn + ni * 8 + lq) * SST + s * 8 + tq;
                bf[ni][0] = Bs[bb];
                bf[ni][1] = Bs[bb + 4];
            }
#pragma unroll
            for (int mi = 0; mi < 4; mi++) {
                const int ab = (wm + mi * 16 + lq) * SST + s * 8 + tq;
                const uint32_t a0 = As[ab];
                const uint32_t a1 = As[ab + 8 * SST];
                const uint32_t a2 = As[ab + 4];
                const uint32_t a3 = As[ab + 8 * SST + 4];
#pragma unroll
                for (int ni = 0; ni < 8; ni++)
                    mma8(acc[mi][ni], a0, a1, a2, a3, bf[ni][0], bf[ni][1]);
            }
        }
        __syncthreads();
        issue(it + 3);
    }

    // ---- epilogue ----
#pragma unroll
    for (int mi = 0; mi < 4; mi++) {
        const int r0 = m0 + wm + mi * 16 + lq;
#pragma unroll
        for (int ni = 0; ni < 8; ni++) {
            const int c0 = n0 + wn + ni * 8 + 2 * tq;
            const float bv0 = bias[c0];
            const float bv1 = bias[c0 + 1];
            float v00 = acc[mi][ni][0] + bv0;
            float v01 = acc[mi][ni][1] + bv1;
            float v10 = acc[mi][ni][2] + bv0;
            float v11 = acc[mi][ni][3] + bv1;
            if (EPI == 1) {
                v00 = rf(gelu_t(v00)); v01 = rf(gelu_t(v01));
                v10 = rf(gelu_t(v10)); v11 = rf(gelu_t(v11));
            }
            if (EPI == 3) {
                __nv_bfloat16* Cb = (__nv_bfloat16*)C;
                const int hh = c0 >> 6, dd = c0 & 63;
                {
                    const int bb = r0 >> 10, ss = r0 & 1023;
                    *(__nv_bfloat162*)&Cb[(size_t)((bb * H_ + hh) * S_ + ss) * DK_ + dd] =
                        __floats2bfloat162_rn(v00, v01);
                }
                {
                    const int r1 = r0 + 8;
                    const int bb = r1 >> 10, ss = r1 & 1023;
                    *(__nv_bfloat162*)&Cb[(size_t)((bb * H_ + hh) * S_ + ss) * DK_ + dd] =
                        __floats2bfloat162_rn(v10, v11);
                }
            } else if (EPI == 4) {
                __nv_bfloat16* Cb = (__nv_bfloat16*)C;
                const int hh = c0 >> 6, dd = c0 & 63;
                const int bb = r0 >> 10, ss = r0 & 1023;
                const size_t base = (size_t)((bb * H_ + hh) * DK_ + dd) * S_ + ss;
                Cb[base]           = __float2bfloat16_rn(v00);
                Cb[base + S_]      = __float2bfloat16_rn(v01);
                Cb[base + 8]       = __float2bfloat16_rn(v10);
                Cb[base + S_ + 8]  = __float2bfloat16_rn(v11);
            } else {
                *(float2*)&C[(size_t)r0 * N + c0]       = make_float2(v00, v01);
                *(float2*)&C[(size_t)(r0 + 8) * N + c0] = make_float2(v10, v11);
            }
        }
    }
}

template <int EPI>
__global__ void __launch_bounds__(128)
mma_gemm(const float* __restrict__ A, const float* __restrict__ Bt,
         const float* __restrict__ bias, float* __restrict__ C,
         int N, int K)
{
    gemm_body<EPI>(A, Bt, bias, C, N, K, blockIdx.y * 128, blockIdx.x * 128);
}

// Q/K projections fused (z = 0/1), bf16 head-split output
__global__ void __launch_bounds__(128)
mma_gemm_qk(const float* __restrict__ A,
            const float* __restrict__ wq, const float* __restrict__ wk,
            const float* __restrict__ bq, const float* __restrict__ bk,
            float* __restrict__ oq, float* __restrict__ ok)
{
    const float* Bt  = blockIdx.z == 0 ? wq : wk;
    const float* bia = blockIdx.z == 0 ? bq : bk;
    float* C         = blockIdx.z == 0 ? oq : ok;
    gemm_body<3>(A, Bt, bia, C, D_, D_, blockIdx.y * 128, blockIdx.x * 128);
}

// ---------------------------------------------------------------------------
// BF16 tensor-core flash attention (output stores tf32-rounded).
// Block = 128 threads (4 warps), each warp owns 16 query rows -> 64 q/CTA.
// ---------------------------------------------------------------------------
__global__ void __launch_bounds__(128)
flash_attn_bf16(const __nv_bfloat16* __restrict__ Q,
                const __nv_bfloat16* __restrict__ K,
                const __nv_bfloat16* __restrict__ Vt,
                const int* __restrict__ mask,
                float* __restrict__ O)
{
    const int qt = blockIdx.x;
    const int h  = blockIdx.y;
    const int b  = blockIdx.z;
    const int tid  = threadIdx.x;
    const int warp = tid >> 5;
    const int lane = tid & 31;
    const int lq = lane >> 2;
    const int tq = lane & 3;
    const int bh = b * H_ + h;

    __shared__ __nv_bfloat16 Ks[128 * 72];
    __shared__ __nv_bfloat16 Vs[64 * 136];
    __shared__ int mk[128];

    {
        const __nv_bfloat16* Qb = Q + (size_t)(bh * S_ + qt * 64) * DK_;
        const int r = tid >> 1, hf = tid & 1;
        const uint4* src = (const uint4*)(Qb + r * DK_ + hf * 32);
        uint4* dst = (uint4*)&Ks[r * 72 + hf * 32];
#pragma unroll
        for (int i = 0; i < 4; i++) dst[i] = src[i];
    }
    __syncthreads();
    uint32_t qa[4][4];
    {
        const int r0 = warp * 16 + lq;
#pragma unroll
        for (int ks = 0; ks < 4; ks++) {
            qa[ks][0] = *(const uint32_t*)&Ks[(r0    ) * 72 + ks * 16 + 2 * tq];
            qa[ks][1] = *(const uint32_t*)&Ks[(r0 + 8) * 72 + ks * 16 + 2 * tq];
            qa[ks][2] = *(const uint32_t*)&Ks[(r0    ) * 72 + ks * 16 + 8 + 2 * tq];
            qa[ks][3] = *(const uint32_t*)&Ks[(r0 + 8) * 72 + ks * 16 + 8 + 2 * tq];
        }
    }
    __syncthreads();

    float o[8][4];
#pragma unroll
    for (int t = 0; t < 8; t++)
#pragma unroll
        for (int j = 0; j < 4; j++) o[t][j] = 0.0f;
    float m0 = -1e30f, m1 = -1e30f, l0 = 0.0f, l1 = 0.0f;

    const __nv_bfloat16* Kb = K  + (size_t)bh * S_ * DK_;
    const __nv_bfloat16* Vb = Vt + (size_t)bh * DK_ * S_;

    for (int kt = 0; kt < 8; kt++) {
        {
            const uint4* src = (const uint4*)(Kb + (size_t)(kt * 128 + tid) * DK_);
            uint4* dst = (uint4*)&Ks[tid * 72];
#pragma unroll
            for (int i = 0; i < 8; i++) dst[i] = src[i];
        }
        {
            const int r = tid >> 1, hf = tid & 1;
            const uint4* src = (const uint4*)(Vb + (size_t)r * S_ + kt * 128 + hf * 64);
            uint4* dst = (uint4*)&Vs[r * 136 + hf * 64];
#pragma unroll
            for (int i = 0; i < 8; i++) dst[i] = src[i];
        }
        mk[tid] = mask[b * S_ + kt * 128 + tid];
        __syncthreads();

        float s[16][4];
#pragma unroll
        for (int nt = 0; nt < 16; nt++) {
            s[nt][0] = s[nt][1] = s[nt][2] = s[nt][3] = 0.0f;
#pragma unroll
            for (int ks = 0; ks < 4; ks++) {
                const uint32_t b0 = *(const uint32_t*)&Ks[(nt * 8 + lq) * 72 + ks * 16 + 2 * tq];
                const uint32_t b1 = *(const uint32_t*)&Ks[(nt * 8 + lq) * 72 + ks * 16 + 8 + 2 * tq];
                mma16(s[nt], qa[ks][0], qa[ks][1], qa[ks][2], qa[ks][3], b0, b1);
            }
        }

        float mx0 = -1e30f, mx1 = -1e30f;
#pragma unroll
        for (int nt = 0; nt < 16; nt++) {
            const int c = nt * 8 + 2 * tq;
            const bool k0 = mk[c] != 0, k1 = mk[c + 1] != 0;
            s[nt][0] = k0 ? s[nt][0] * 0.125f : -1e9f;
            s[nt][1] = k1 ? s[nt][1] * 0.125f : -1e9f;
            s[nt][2] = k0 ? s[nt][2] * 0.125f : -1e9f;
            s[nt][3] = k1 ? s[nt][3] * 0.125f : -1e9f;
            mx0 = fmaxf(mx0, fmaxf(s[nt][0], s[nt][1]));
            mx1 = fmaxf(mx1, fmaxf(s[nt][2], s[nt][3]));
        }
        mx0 = fmaxf(mx0, __shfl_xor_sync(0xffffffffu, mx0, 1));
        mx0 = fmaxf(mx0, __shfl_xor_sync(0xffffffffu, mx0, 2));
        mx1 = fmaxf(mx1, __shfl_xor_sync(0xffffffffu, mx1, 1));
        mx1 = fmaxf(mx1, __shfl_xor_sync(0xffffffffu, mx1, 2));

        const float nm0 = fmaxf(m0, mx0);
        const float nm1 = fmaxf(m1, mx1);
        const float al0 = __expf(m0 - nm0);
        const float al1 = __expf(m1 - nm1);
        m0 = nm0; m1 = nm1;

        float ps0 = 0.0f, ps1 = 0.0f;
#pragma unroll
        for (int nt = 0; nt < 16; nt++) {
            s[nt][0] = __expf(s[nt][0] - m0);
            s[nt][1] = __expf(s[nt][1] - m0);
            s[nt][2] = __expf(s[nt][2] - m1);
            s[nt][3] = __expf(s[nt][3] - m1);
            ps0 += s[nt][0] + s[nt][1];
            ps1 += s[nt][2] + s[nt][3];
        }
        ps0 += __shfl_xor_sync(0xffffffffu, ps0, 1);
        ps0 += __shfl_xor_sync(0xffffffffu, ps0, 2);
        ps1 += __shfl_xor_sync(0xffffffffu, ps1, 1);
        ps1 += __shfl_xor_sync(0xffffffffu, ps1, 2);
        l0 = l0 * al0 + ps0;
        l1 = l1 * al1 + ps1;

#pragma unroll
        for (int t = 0; t < 8; t++) {
            o[t][0] *= al0; o[t][1] *= al0;
            o[t][2] *= al1; o[t][3] *= al1;
        }

#pragma unroll
        for (int kc = 0; kc < 8; kc++) {
            const uint32_t a0 = pack_bf16(s[2 * kc][0],     s[2 * kc][1]);
            const uint32_t a1 = pack_bf16(s[2 * kc][2],     s[2 * kc][3]);
            const uint32_t a2 = pack_bf16(s[2 * kc + 1][0], s[2 * kc + 1][1]);
            const uint32_t a3 = pack_bf16(s[2 * kc + 1][2], s[2 * kc + 1][3]);
#pragma unroll
            for (int t = 0; t < 8; t++) {
                const uint32_t b0 = *(const uint32_t*)&Vs[(t * 8 + lq) * 136 + kc * 16 + 2 * tq];
                const uint32_t b1 = *(const uint32_t*)&Vs[(t * 8 + lq) * 136 + kc * 16 + 8 + 2 * tq];
                mma16(o[t], a0, a1, a2, a3, b0, b1);
            }
        }
        __syncthreads();
    }

    // tf32-rounded fp32 output (feeds Wo GEMM A-operand)
    const float i0 = 1.0f / l0;
    const float i1 = 1.0f / l1;
    const int qr = qt * 64 + warp * 16 + lq;
    float* O0 = O + (size_t)(b * S_ + qr) * D_ + h * DK_;
    float* O1 = O0 + (size_t)8 * D_;
#pragma unroll
    for (int t = 0; t < 8; t++) {
        *(float2*)(O0 + t * 8 + 2 * tq) = make_float2(rf(o[t][0] * i0), rf(o[t][1] * i0));
        *(float2*)(O1 + t * 8 + 2 * tq) = make_float2(rf(o[t][2] * i1), rf(o[t][3] * i1));
    }
}

// ---------------------------------------------------------------------------
// Fused residual add + LayerNorm; optionally writes tf32-rounded copy.
// ---------------------------------------------------------------------------
template <bool WR>
__global__ void __launch_bounds__(256)
ln_residual_kernel(const float* __restrict__ X, const float* __restrict__ R,
                   const float* __restrict__ ga, const float* __restrict__ gb,
                   float* __restrict__ out, float* __restrict__ outr)
{
    const int row = blockIdx.x;
    const int t   = threadIdx.x;
    const float* xr = X + (size_t)row * D_;
    const float* rr = R + (size_t)row * D_;

    float v[3];
#pragma unroll
    for (int i = 0; i < 3; i++) v[i] = xr[t + i * 256] + rr[t + i * 256];

    __shared__ float sbuf[8];

    float s = v[0] + v[1] + v[2];
#pragma unroll
    for (int off = 16; off > 0; off >>= 1) s += __shfl_xor_sync(0xffffffffu, s, off);
    if ((t & 31) == 0) sbuf[t >> 5] = s;
    __syncthreads();
    float tot = 0.f;
#pragma unroll
    for (int i = 0; i < 8; i++) tot += sbuf[i];
    const float mean = tot * (1.0f / (float)D_);
    __syncthreads();

    float d0 = v[0] - mean, d1 = v[1] - mean, d2 = v[2] - mean;
    float sq = d0 * d0 + d1 * d1 + d2 * d2;
#pragma unroll
    for (int off = 16; off > 0; off >>= 1) sq += __shfl_xor_sync(0xffffffffu, sq, off);
    if ((t & 31) == 0) sbuf[t >> 5] = sq;
    __syncthreads();
    float tot2 = 0.f;
#pragma unroll
    for (int i = 0; i < 8; i++) tot2 += sbuf[i];
    const float var = tot2 * (1.0f / (float)(D_ - 1));
    const float inv = 1.0f / (sqrtf(var) + 1e-6f);

    float* orow = out + (size_t)row * D_;
    const float o0 = ga[t      ] * d0 * inv + gb[t      ];
    const float o1 = ga[t + 256] * d1 * inv + gb[t + 256];
    const float o2 = ga[t + 512] * d2 * inv + gb[t + 512];
    orow[t      ] = o0;
    orow[t + 256] = o1;
    orow[t + 512] = o2;
    if (WR) {
        float* orr = outr + (size_t)row * D_;
        orr[t      ] = rf(o0);
        orr[t + 256] = rf(o1);
        orr[t + 512] = rf(o2);
    }
}

// ---------------------------------------------------------------------------
// Launch
// ---------------------------------------------------------------------------
extern "C" void kernel_launch(void* const* d_in, const int* in_sizes, int n_in,
                              void* d_out, int out_size)
{
    const float* x    = (const float*)d_in[0];
    const int*   mask = (const int*)  d_in[1];
    const float* Wq   = (const float*)d_in[2];
    const float* bq   = (const float*)d_in[3];
    const float* Wk   = (const float*)d_in[4];
    const float* bk   = (const float*)d_in[5];
    const float* Wv   = (const float*)d_in[6];
    const float* bv   = (const float*)d_in[7];
    const float* Wo   = (const float*)d_in[8];
    const float* bo   = (const float*)d_in[9];
    const float* W1   = (const float*)d_in[10];
    const float* b1   = (const float*)d_in[11];
    const float* W2   = (const float*)d_in[12];
    const float* b2   = (const float*)d_in[13];
    const float* ln1a = (const float*)d_in[14];
    const float* ln1b = (const float*)d_in[15];
    const float* ln2a = (const float*)d_in[16];
    const float* ln2b = (const float*)d_in[17];

    __nv_bfloat16 *qb, *kb, *vtb;
    float *xr, *att, *tmp, *out1, *o1r, *ffh;
    float *wqT, *wkT, *wvT, *woT, *w1T, *w2T;
    cudaGetSymbolAddress((void**)&qb,   g_qb);
    cudaGetSymbolAddress((void**)&kb,   g_kb);
    cudaGetSymbolAddress((void**)&vtb,  g_vtb);
    cudaGetSymbolAddress((void**)&xr,   g_xr);
    cudaGetSymbolAddress((void**)&att,  g_att);
    cudaGetSymbolAddress((void**)&tmp,  g_tmp);
    cudaGetSymbolAddress((void**)&out1, g_out1);
    cudaGetSymbolAddress((void**)&o1r,  g_o1r);
    cudaGetSymbolAddress((void**)&ffh,  g_ffh);
    cudaGetSymbolAddress((void**)&wqT,  g_wqT);
    cudaGetSymbolAddress((void**)&wkT,  g_wkT);
    cudaGetSymbolAddress((void**)&wvT,  g_wvT);
    cudaGetSymbolAddress((void**)&woT,  g_woT);
    cudaGetSymbolAddress((void**)&w1T,  g_w1T);
    cudaGetSymbolAddress((void**)&w2T,  g_w2T);

    cudaFuncSetAttribute(mma_gemm<0>, cudaFuncAttributeMaxDynamicSharedMemorySize, GEMM_SMEM);
    cudaFuncSetAttribute(mma_gemm<1>, cudaFuncAttributeMaxDynamicSharedMemorySize, GEMM_SMEM);
    cudaFuncSetAttribute(mma_gemm<4>, cudaFuncAttributeMaxDynamicSharedMemorySize, GEMM_SMEM);
    cudaFuncSetAttribute(mma_gemm_qk, cudaFuncAttributeMaxDynamicSharedMemorySize, GEMM_SMEM);

    // x -> tf32 copy
    round_x_kernel<<<(M_ * D_) / 4 / 256, 256>>>((const float4*)x, (float4*)xr);

    // Weight transposes (tf32-rounded)
    dim3 tb(32, 8);
    transpose_qkvo<<<dim3(D_ / 32, D_ / 32, 4), tb>>>(Wq, Wk, Wv, Wo, wqT, wkT, wvT, woT);
    transpose_k<<<dim3(D_ / 32, F_ / 32), tb>>>(W1, w1T, D_, F_);
    transpose_k<<<dim3(F_ / 32, D_ / 32), tb>>>(W2, w2T, F_, D_);

    dim3 gProj(D_ / 128, M_ / 128);          // (6, 64)
    dim3 gQk  (D_ / 128, M_ / 128, 2);       // (6, 64, 2)
    dim3 gFfn1(F_ / 128, M_ / 128);          // (24, 64)

    // Q,K projections (bf16 head-split) + V projection (bf16 transposed)
    mma_gemm_qk<<<gQk, 128, GEMM_SMEM>>>(xr, wqT, wkT, bq, bk, (float*)qb, (float*)kb);
    mma_gemm<4><<<gProj, 128, GEMM_SMEM>>>(xr, wvT, bv, (float*)vtb, D_, D_);

    // Attention (bf16 tensor cores, tf32-rounded output)
    dim3 gAttn(S_ / 64, H_, B_);
    flash_attn_bf16<<<gAttn, 128>>>(qb, kb, vtb, mask, att);

    // Output projection
    mma_gemm<0><<<gProj, 128, GEMM_SMEM>>>(att, woT, bo, tmp, D_, D_);

    // LN1(x + attn_out) -> out1 (fp32) + o1r (tf32)
    ln_residual_kernel<true><<<M_, 256>>>(x, tmp, ln1a, ln1b, out1, o1r);

    // FFN
    mma_gemm<1><<<gFfn1, 128, GEMM_SMEM>>>(o1r, w1T, b1, ffh, F_, D_);
    mma_gemm<0><<<gProj, 128, GEMM_SMEM>>>(ffh, w2T, b2, tmp, D_, F_);

    // LN2(out1 + ffn) -> output
    ln_residual_kernel<false><<<M_, 256>>>(out1, tmp, ln2a, ln2b, (float*)d_out, nullptr);
}

// round 6
// speedup vs baseline: 5.1247x; 1.3174x over previous
#include <cuda_runtime.h>
#include <cuda_bf16.h>
#include <math.h>
#include <stdint.h>

// ---------------------------------------------------------------------------
// Problem constants
// ---------------------------------------------------------------------------
#define B_   8
#define S_   1024
#define D_   768
#define F_   3072
#define H_   12
#define DK_  64
#define M_   (B_ * S_)       // 8192 rows

// ---------------------------------------------------------------------------
// Scratch (device globals; no allocation allowed)
// ---------------------------------------------------------------------------
__device__ __align__(16) __nv_bfloat16 g_xb [M_ * D_];              // x bf16
__device__ __align__(16) __nv_bfloat16 g_qb [B_ * H_ * S_ * DK_];   // [B,H,S,dk]
__device__ __align__(16) __nv_bfloat16 g_kb [B_ * H_ * S_ * DK_];   // [B,H,S,dk]
__device__ __align__(16) __nv_bfloat16 g_vtb[B_ * H_ * DK_ * S_];   // [B,H,dk,S]
__device__ __align__(16) __nv_bfloat16 g_att[M_ * D_];              // attn out bf16
__device__ __align__(16) __nv_bfloat16 g_ffh[M_ * F_];              // gelu out bf16
__device__ __align__(16) float g_tmp [M_ * D_];    // fp32 scratch
__device__ __align__(16) float g_out1[M_ * D_];    // LN1 out fp32
__device__ __align__(16) float g_o1r [M_ * D_];    // LN1 out tf32
// transposed weights, [N, K] K-major
__device__ __align__(16) __nv_bfloat16 g_wqT[D_ * D_];
__device__ __align__(16) __nv_bfloat16 g_wkT[D_ * D_];
__device__ __align__(16) __nv_bfloat16 g_wvT[D_ * D_];
__device__ __align__(16) __nv_bfloat16 g_woT[D_ * D_];
__device__ __align__(16) __nv_bfloat16 g_w2T[D_ * F_];
__device__ __align__(16) float g_w1T[F_ * D_];     // tf32-rounded

// ---------------------------------------------------------------------------
// Helpers
// ---------------------------------------------------------------------------
__device__ __forceinline__ uint32_t smem_u32(const void* p) {
    uint32_t a;
    asm("{ .reg .u64 t; cvta.to.shared.u64 t, %1; cvt.u32.u64 %0, t; }"
        : "=r"(a) : "l"(p));
    return a;
}
__device__ __forceinline__ uint32_t rna_tf32(float x) {
    uint32_t r;
    asm("cvt.rna.tf32.f32 %0, %1;" : "=r"(r) : "f"(x));
    return r;
}
__device__ __forceinline__ float rf(float x) { return __uint_as_float(rna_tf32(x)); }

__device__ __forceinline__ void cp16(uint32_t dst, const void* src) {
    asm volatile("cp.async.cg.shared.global [%0], [%1], 16;"
                 :: "r"(dst), "l"(src) : "memory");
}
#define CP_COMMIT asm volatile("cp.async.commit_group;" ::: "memory")
#define CP_WAIT2  asm volatile("cp.async.wait_group 2;" ::: "memory")

// m16n8k8 TF32 MMA
__device__ __forceinline__ void mma8(float* c,
                                     uint32_t a0, uint32_t a1, uint32_t a2, uint32_t a3,
                                     uint32_t b0, uint32_t b1)
{
    asm volatile(
        "mma.sync.aligned.m16n8k8.row.col.f32.tf32.tf32.f32 "
        "{%0,%1,%2,%3}, {%4,%5,%6,%7}, {%8,%9}, {%0,%1,%2,%3};"
        : "+f"(c[0]), "+f"(c[1]), "+f"(c[2]), "+f"(c[3])
        : "r"(a0), "r"(a1), "r"(a2), "r"(a3), "r"(b0), "r"(b1));
}

// m16n8k16 BF16 MMA
__device__ __forceinline__ void mma16(float* c,
                                      uint32_t a0, uint32_t a1, uint32_t a2, uint32_t a3,
                                      uint32_t b0, uint32_t b1)
{
    asm volatile(
        "mma.sync.aligned.m16n8k16.row.col.f32.bf16.bf16.f32 "
        "{%0,%1,%2,%3}, {%4,%5,%6,%7}, {%8,%9}, {%0,%1,%2,%3};"
        : "+f"(c[0]), "+f"(c[1]), "+f"(c[2]), "+f"(c[3])
        : "r"(a0), "r"(a1), "r"(a2), "r"(a3), "r"(b0), "r"(b1));
}

__device__ __forceinline__ uint32_t pack_bf16(float lo, float hi) {
    uint32_t r;
    asm("cvt.rn.bf16x2.f32 %0, %1, %2;" : "=r"(r) : "f"(hi), "f"(lo));
    return r;
}

__device__ __forceinline__ float gelu_t(float x) {
    const float c = 0.7978845608028654f;
    float t = tanhf(c * (x + 0.044715f * x * x * x));
    return 0.5f * x * (1.0f + t);
}

// ---------------------------------------------------------------------------
// x -> bf16 copy
// ---------------------------------------------------------------------------
__global__ void __launch_bounds__(256)
round_xb_kernel(const float4* __restrict__ in, uint2* __restrict__ out)
{
    const int i = blockIdx.x * 256 + threadIdx.x;
    float4 v = in[i];
    uint2 o;
    o.x = pack_bf16(v.x, v.y);
    o.y = pack_bf16(v.z, v.w);
    out[i] = o;
}

// ---------------------------------------------------------------------------
// Weight transposes W[K,N] -> Wt[N,K]; bf16 or tf32 output
// ---------------------------------------------------------------------------
__device__ __forceinline__ void transpose_body_bf16(
    const float* __restrict__ W, __nv_bfloat16* __restrict__ Wt, int K, int N)
{
    __shared__ float t[32][33];
    const int k0 = blockIdx.x * 32;
    const int n0 = blockIdx.y * 32;
    const int x = threadIdx.x;
    const int y = threadIdx.y;
#pragma unroll
    for (int i = 0; i < 32; i += 8)
        t[y + i][x] = W[(size_t)(k0 + y + i) * N + n0 + x];
    __syncthreads();
#pragma unroll
    for (int i = 0; i < 32; i += 8)
        Wt[(size_t)(n0 + y + i) * K + k0 + x] = __float2bfloat16_rn(t[x][y + i]);
}

__global__ void __launch_bounds__(256)
transpose_tf32(const float* __restrict__ W, float* __restrict__ Wt, int K, int N)
{
    __shared__ float t[32][33];
    const int k0 = blockIdx.x * 32;
    const int n0 = blockIdx.y * 32;
    const int x = threadIdx.x;
    const int y = threadIdx.y;
#pragma unroll
    for (int i = 0; i < 32; i += 8)
        t[y + i][x] = W[(size_t)(k0 + y + i) * N + n0 + x];
    __syncthreads();
#pragma unroll
    for (int i = 0; i < 32; i += 8)
        Wt[(size_t)(n0 + y + i) * K + k0 + x] = rf(t[x][y + i]);
}

__global__ void __launch_bounds__(256)
transpose_b16(const float* __restrict__ W, __nv_bfloat16* __restrict__ Wt, int K, int N)
{
    transpose_body_bf16(W, Wt, K, N);
}

__global__ void __launch_bounds__(256)
transpose_qkvo(const float* __restrict__ Wq, const float* __restrict__ Wk,
               const float* __restrict__ Wv, const float* __restrict__ Wo,
               __nv_bfloat16* __restrict__ oq, __nv_bfloat16* __restrict__ ok,
               __nv_bfloat16* __restrict__ ov, __nv_bfloat16* __restrict__ oo)
{
    const float* W; __nv_bfloat16* Wt;
    if (blockIdx.z == 0)      { W = Wq; Wt = oq; }
    else if (blockIdx.z == 1) { W = Wk; Wt = ok; }
    else if (blockIdx.z == 2) { W = Wv; Wt = ov; }
    else                      { W = Wo; Wt = oo; }
    transpose_body_bf16(W, Wt, D_, D_);
}

// ---------------------------------------------------------------------------
// Shared epilogue (fp32 accumulators -> various output formats)
//   EPI: 0 plain fp32, 3 bf16 head-split [B,H,S,dk],
//        4 bf16 transposed head-split [B,H,dk,S], 5 gelu -> bf16 row-major
// ---------------------------------------------------------------------------
template <int EPI>
__device__ __forceinline__ void epilogue(
    float acc[4][8][4], const float* __restrict__ bias, void* __restrict__ C,
    int N, int m0, int n0, int wm, int wn, int lq, int tq)
{
#pragma unroll
    for (int mi = 0; mi < 4; mi++) {
        const int r0 = m0 + wm + mi * 16 + lq;
#pragma unroll
        for (int ni = 0; ni < 8; ni++) {
            const int c0 = n0 + wn + ni * 8 + 2 * tq;
            const float bv0 = bias[c0];
            const float bv1 = bias[c0 + 1];
            float v00 = acc[mi][ni][0] + bv0;
            float v01 = acc[mi][ni][1] + bv1;
            float v10 = acc[mi][ni][2] + bv0;
            float v11 = acc[mi][ni][3] + bv1;
            if (EPI == 5) {
                v00 = gelu_t(v00); v01 = gelu_t(v01);
                v10 = gelu_t(v10); v11 = gelu_t(v11);
            }
            if (EPI == 3) {
                __nv_bfloat16* Cb = (__nv_bfloat16*)C;
                const int hh = c0 >> 6, dd = c0 & 63;
                {
                    const int bb = r0 >> 10, ss = r0 & 1023;
                    *(__nv_bfloat162*)&Cb[(size_t)((bb * H_ + hh) * S_ + ss) * DK_ + dd] =
                        __floats2bfloat162_rn(v00, v01);
                }
                {
                    const int r1 = r0 + 8;
                    const int bb = r1 >> 10, ss = r1 & 1023;
                    *(__nv_bfloat162*)&Cb[(size_t)((bb * H_ + hh) * S_ + ss) * DK_ + dd] =
                        __floats2bfloat162_rn(v10, v11);
                }
            } else if (EPI == 4) {
                __nv_bfloat16* Cb = (__nv_bfloat16*)C;
                const int hh = c0 >> 6, dd = c0 & 63;
                const int bb = r0 >> 10, ss = r0 & 1023;
                const size_t base = (size_t)((bb * H_ + hh) * DK_ + dd) * S_ + ss;
                Cb[base]           = __float2bfloat16_rn(v00);
                Cb[base + S_]      = __float2bfloat16_rn(v01);
                Cb[base + 8]       = __float2bfloat16_rn(v10);
                Cb[base + S_ + 8]  = __float2bfloat16_rn(v11);
            } else if (EPI == 5) {
                __nv_bfloat16* Cb = (__nv_bfloat16*)C;
                *(__nv_bfloat162*)&Cb[(size_t)r0 * N + c0]       = __floats2bfloat162_rn(v00, v01);
                *(__nv_bfloat162*)&Cb[(size_t)(r0 + 8) * N + c0] = __floats2bfloat162_rn(v10, v11);
            } else {
                float* Cf = (float*)C;
                *(float2*)&Cf[(size_t)r0 * N + c0]       = make_float2(v00, v01);
                *(float2*)&Cf[(size_t)(r0 + 8) * N + c0] = make_float2(v10, v11);
            }
        }
    }
}

// ---------------------------------------------------------------------------
// TF32 mma.sync GEMM, cp.async 3-stage pipeline (FFN1 only).
//   CTA 128x128, 128 threads, warp tile 64x64, BK=32.
// ---------------------------------------------------------------------------
#define SST  36
#define STGW (128 * SST)
#define STGB (STGW * 4)              // 18432
#define GEMM_SMEM (6 * STGB)         // 110592

template <int EPI>
__device__ __forceinline__ void gemm_tf32_body(
    const float* __restrict__ A, const float* __restrict__ Bt,
    const float* __restrict__ bias, void* __restrict__ C,
    int N, int K, int m0, int n0)
{
    extern __shared__ uint32_t sm[];
    const uint32_t sbase = smem_u32(sm);

    const int tid  = threadIdx.x;
    const int warp = tid >> 5;
    const int lane = tid & 31;
    const int wm = (warp >> 1) * 64;
    const int wn = (warp & 1) * 64;
    const int lq = lane >> 2;
    const int tq = lane & 3;

    const int rr = tid >> 3;
    const int cc = (tid & 7) * 4;

    const float* Ap = A  + (size_t)(m0 + rr) * K + cc;
    const float* Bp = Bt + (size_t)(n0 + rr) * K + cc;
    const uint32_t dA = sbase + (uint32_t)(rr * SST + cc) * 4;
    const uint32_t dB = dA + 3 * STGB;

    const int KIT = K >> 5;

    float acc[4][8][4];
#pragma unroll
    for (int mi = 0; mi < 4; mi++)
#pragma unroll
        for (int ni = 0; ni < 8; ni++)
#pragma unroll
            for (int j = 0; j < 4; j++) acc[mi][ni][j] = 0.0f;

    auto issue = [&](int it) {
        if (it < KIT) {
            const float* a = Ap + it * 32;
            const float* b = Bp + it * 32;
            const uint32_t off = (uint32_t)(it % 3) * STGB;
#pragma unroll
            for (int i = 0; i < 8; i++) {
                cp16(dA + off + (uint32_t)(i * 16 * SST) * 4, a + (size_t)(i * 16) * K);
                cp16(dB + off + (uint32_t)(i * 16 * SST) * 4, b + (size_t)(i * 16) * K);
            }
        }
        CP_COMMIT;
    };

    issue(0); issue(1); issue(2);

    for (int it = 0; it < KIT; ++it) {
        CP_WAIT2;
        __syncthreads();
        const uint32_t* As = sm + (it % 3) * STGW;
        const uint32_t* Bs = As + 3 * STGW;

#pragma unroll
        for (int s = 0; s < 4; ++s) {
            uint32_t bf[8][2];
#pragma unroll
            for (int ni = 0; ni < 8; ni++) {
                const int bb = (wn + ni * 8 + lq) * SST + s * 8 + tq;
                bf[ni][0] = Bs[bb];
                bf[ni][1] = Bs[bb + 4];
            }
#pragma unroll
            for (int mi = 0; mi < 4; mi++) {
                const int ab = (wm + mi * 16 + lq) * SST + s * 8 + tq;
                const uint32_t a0 = As[ab];
                const uint32_t a1 = As[ab + 8 * SST];
                const uint32_t a2 = As[ab + 4];
                const uint32_t a3 = As[ab + 8 * SST + 4];
#pragma unroll
                for (int ni = 0; ni < 8; ni++)
                    mma8(acc[mi][ni], a0, a1, a2, a3, bf[ni][0], bf[ni][1]);
            }
        }
        __syncthreads();
        issue(it + 3);
    }

    epilogue<EPI>(acc, bias, C, N, m0, n0, wm, wn, lq, tq);
}

template <int EPI>
__global__ void __launch_bounds__(128)
mma_gemm_t(const float* __restrict__ A, const float* __restrict__ Bt,
           const float* __restrict__ bias, void* __restrict__ C,
           int N, int K)
{
    gemm_tf32_body<EPI>(A, Bt, bias, C, N, K, blockIdx.y * 128, blockIdx.x * 128);
}

// ---------------------------------------------------------------------------
// BF16 mma.sync GEMM, cp.async 3-stage pipeline.
//   CTA 128x128, 128 threads, warp tile 64x64, BK=64.
//   Smem: 128 rows x 72 halves per operand stage (stride-72 conflict-free).
// ---------------------------------------------------------------------------
#define HST   72                     // halves per row
#define HSTGH (128 * HST)            // halves per stage = 9216
#define HSTGB (HSTGH * 2)            // 18432 bytes

template <int EPI>
__device__ __forceinline__ void gemm_bf16_body(
    const __nv_bfloat16* __restrict__ A, const __nv_bfloat16* __restrict__ Bt,
    const float* __restrict__ bias, void* __restrict__ C,
    int N, int K, int m0, int n0)
{
    extern __shared__ __nv_bfloat16 smh[];
    const uint32_t sbase = smem_u32(smh);

    const int tid  = threadIdx.x;
    const int warp = tid >> 5;
    const int lane = tid & 31;
    const int wm = (warp >> 1) * 64;
    const int wn = (warp & 1) * 64;
    const int lq = lane >> 2;
    const int tq = lane & 3;

    const int rr  = tid >> 3;            // 0..15
    const int cc8 = (tid & 7) * 8;       // halves, 0..56

    const __nv_bfloat16* Ap = A  + (size_t)(m0 + rr) * K + cc8;
    const __nv_bfloat16* Bp = Bt + (size_t)(n0 + rr) * K + cc8;
    const uint32_t dA = sbase + (uint32_t)(rr * HST + cc8) * 2;
    const uint32_t dB = dA + 3 * HSTGB;

    const int KIT = K >> 6;

    float acc[4][8][4];
#pragma unroll
    for (int mi = 0; mi < 4; mi++)
#pragma unroll
        for (int ni = 0; ni < 8; ni++)
#pragma unroll
            for (int j = 0; j < 4; j++) acc[mi][ni][j] = 0.0f;

    auto issue = [&](int it) {
        if (it < KIT) {
            const __nv_bfloat16* a = Ap + it * 64;
            const __nv_bfloat16* b = Bp + it * 64;
            const uint32_t off = (uint32_t)(it % 3) * HSTGB;
#pragma unroll
            for (int i = 0; i < 8; i++) {
                cp16(dA + off + (uint32_t)(i * 16 * HST) * 2, a + (size_t)(i * 16) * K);
                cp16(dB + off + (uint32_t)(i * 16 * HST) * 2, b + (size_t)(i * 16) * K);
            }
        }
        CP_COMMIT;
    };

    issue(0); issue(1); issue(2);

    for (int it = 0; it < KIT; ++it) {
        CP_WAIT2;
        __syncthreads();
        const __nv_bfloat16* As = smh + (it % 3) * HSTGH;
        const __nv_bfloat16* Bs = As + 3 * HSTGH;

#pragma unroll
        for (int s = 0; s < 4; ++s) {     // 4 x k16
            uint32_t bf[8][2];
#pragma unroll
            for (int ni = 0; ni < 8; ni++) {
                const int bb = (wn + ni * 8 + lq) * HST + s * 16 + 2 * tq;
                bf[ni][0] = *(const uint32_t*)&Bs[bb];
                bf[ni][1] = *(const uint32_t*)&Bs[bb + 8];
            }
#pragma unroll
            for (int mi = 0; mi < 4; mi++) {
                const int ab = (wm + mi * 16 + lq) * HST + s * 16 + 2 * tq;
                const uint32_t a0 = *(const uint32_t*)&As[ab];
                const uint32_t a1 = *(const uint32_t*)&As[ab + 8 * HST];
                const uint32_t a2 = *(const uint32_t*)&As[ab + 8];
                const uint32_t a3 = *(const uint32_t*)&As[ab + 8 * HST + 8];
#pragma unroll
                for (int ni = 0; ni < 8; ni++)
                    mma16(acc[mi][ni], a0, a1, a2, a3, bf[ni][0], bf[ni][1]);
            }
        }
        __syncthreads();
        issue(it + 3);
    }

    epilogue<EPI>(acc, bias, C, N, m0, n0, wm, wn, lq, tq);
}

template <int EPI>
__global__ void __launch_bounds__(128)
mma_gemm_b(const __nv_bfloat16* __restrict__ A, const __nv_bfloat16* __restrict__ Bt,
           const float* __restrict__ bias, void* __restrict__ C,
           int N, int K)
{
    gemm_bf16_body<EPI>(A, Bt, bias, C, N, K, blockIdx.y * 128, blockIdx.x * 128);
}

// Q/K projections fused (z = 0/1), bf16 head-split output
__global__ void __launch_bounds__(128)
mma_gemm_b_qk(const __nv_bfloat16* __restrict__ A,
              const __nv_bfloat16* __restrict__ wq, const __nv_bfloat16* __restrict__ wk,
              const float* __restrict__ bq, const float* __restrict__ bk,
              __nv_bfloat16* __restrict__ oq, __nv_bfloat16* __restrict__ ok)
{
    const __nv_bfloat16* Bt = blockIdx.z == 0 ? wq : wk;
    const float* bia        = blockIdx.z == 0 ? bq : bk;
    __nv_bfloat16* C        = blockIdx.z == 0 ? oq : ok;
    gemm_bf16_body<3>(A, Bt, bia, C, D_, D_, blockIdx.y * 128, blockIdx.x * 128);
}

// ---------------------------------------------------------------------------
// BF16 tensor-core flash attention; output stored bf16 [B,S,D].
// ---------------------------------------------------------------------------
__global__ void __launch_bounds__(128)
flash_attn_bf16(const __nv_bfloat16* __restrict__ Q,
                const __nv_bfloat16* __restrict__ K,
                const __nv_bfloat16* __restrict__ Vt,
                const int* __restrict__ mask,
                __nv_bfloat16* __restrict__ O)
{
    const int qt = blockIdx.x;
    const int h  = blockIdx.y;
    const int b  = blockIdx.z;
    const int tid  = threadIdx.x;
    const int warp = tid >> 5;
    const int lane = tid & 31;
    const int lq = lane >> 2;
    const int tq = lane & 3;
    const int bh = b * H_ + h;

    __shared__ __nv_bfloat16 Ks[128 * 72];
    __shared__ __nv_bfloat16 Vs[64 * 136];
    __shared__ int mk[128];

    {
        const __nv_bfloat16* Qb = Q + (size_t)(bh * S_ + qt * 64) * DK_;
        const int r = tid >> 1, hf = tid & 1;
        const uint4* src = (const uint4*)(Qb + r * DK_ + hf * 32);
        uint4* dst = (uint4*)&Ks[r * 72 + hf * 32];
#pragma unroll
        for (int i = 0; i < 4; i++) dst[i] = src[i];
    }
    __syncthreads();
    uint32_t qa[4][4];
    {
        const int r0 = warp * 16 + lq;
#pragma unroll
        for (int ks = 0; ks < 4; ks++) {
            qa[ks][0] = *(const uint32_t*)&Ks[(r0    ) * 72 + ks * 16 + 2 * tq];
            qa[ks][1] = *(const uint32_t*)&Ks[(r0 + 8) * 72 + ks * 16 + 2 * tq];
            qa[ks][2] = *(const uint32_t*)&Ks[(r0    ) * 72 + ks * 16 + 8 + 2 * tq];
            qa[ks][3] = *(const uint32_t*)&Ks[(r0 + 8) * 72 + ks * 16 + 8 + 2 * tq];
        }
    }
    __syncthreads();

    float o[8][4];
#pragma unroll
    for (int t = 0; t < 8; t++)
#pragma unroll
        for (int j = 0; j < 4; j++) o[t][j] = 0.0f;
    float m0 = -1e30f, m1 = -1e30f, l0 = 0.0f, l1 = 0.0f;

    const __nv_bfloat16* Kb = K  + (size_t)bh * S_ * DK_;
    const __nv_bfloat16* Vb = Vt + (size_t)bh * DK_ * S_;

    for (int kt = 0; kt < 8; kt++) {
        {
            const uint4* src = (const uint4*)(Kb + (size_t)(kt * 128 + tid) * DK_);
            uint4* dst = (uint4*)&Ks[tid * 72];
#pragma unroll
            for (int i = 0; i < 8; i++) dst[i] = src[i];
        }
        {
            const int r = tid >> 1, hf = tid & 1;
            const uint4* src = (const uint4*)(Vb + (size_t)r * S_ + kt * 128 + hf * 64);
            uint4* dst = (uint4*)&Vs[r * 136 + hf * 64];
#pragma unroll
            for (int i = 0; i < 8; i++) dst[i] = src[i];
        }
        mk[tid] = mask[b * S_ + kt * 128 + tid];
        __syncthreads();

        float s[16][4];
#pragma unroll
        for (int nt = 0; nt < 16; nt++) {
            s[nt][0] = s[nt][1] = s[nt][2] = s[nt][3] = 0.0f;
#pragma unroll
            for (int ks = 0; ks < 4; ks++) {
                const uint32_t b0 = *(const uint32_t*)&Ks[(nt * 8 + lq) * 72 + ks * 16 + 2 * tq];
                const uint32_t b1 = *(const uint32_t*)&Ks[(nt * 8 + lq) * 72 + ks * 16 + 8 + 2 * tq];
                mma16(s[nt], qa[ks][0], qa[ks][1], qa[ks][2], qa[ks][3], b0, b1);
            }
        }

        float mx0 = -1e30f, mx1 = -1e30f;
#pragma unroll
        for (int nt = 0; nt < 16; nt++) {
            const int c = nt * 8 + 2 * tq;
            const bool k0 = mk[c] != 0, k1 = mk[c + 1] != 0;
            s[nt][0] = k0 ? s[nt][0] * 0.125f : -1e9f;
            s[nt][1] = k1 ? s[nt][1] * 0.125f : -1e9f;
            s[nt][2] = k0 ? s[nt][2] * 0.125f : -1e9f;
            s[nt][3] = k1 ? s[nt][3] * 0.125f : -1e9f;
            mx0 = fmaxf(mx0, fmaxf(s[nt][0], s[nt][1]));
            mx1 = fmaxf(mx1, fmaxf(s[nt][2], s[nt][3]));
        }
        mx0 = fmaxf(mx0, __shfl_xor_sync(0xffffffffu, mx0, 1));
        mx0 = fmaxf(mx0, __shfl_xor_sync(0xffffffffu, mx0, 2));
        mx1 = fmaxf(mx1, __shfl_xor_sync(0xffffffffu, mx1, 1));
        mx1 = fmaxf(mx1, __shfl_xor_sync(0xffffffffu, mx1, 2));

        const float nm0 = fmaxf(m0, mx0);
        const float nm1 = fmaxf(m1, mx1);
        const float al0 = __expf(m0 - nm0);
        const float al1 = __expf(m1 - nm1);
        m0 = nm0; m1 = nm1;

        float ps0 = 0.0f, ps1 = 0.0f;
#pragma unroll
        for (int nt = 0; nt < 16; nt++) {
            s[nt][0] = __expf(s[nt][0] - m0);
            s[nt][1] = __expf(s[nt][1] - m0);
            s[nt][2] = __expf(s[nt][2] - m1);
            s[nt][3] = __expf(s[nt][3] - m1);
            ps0 += s[nt][0] + s[nt][1];
            ps1 += s[nt][2] + s[nt][3];
        }
        ps0 += __shfl_xor_sync(0xffffffffu, ps0, 1);
        ps0 += __shfl_xor_sync(0xffffffffu, ps0, 2);
        ps1 += __shfl_xor_sync(0xffffffffu, ps1, 1);
        ps1 += __shfl_xor_sync(0xffffffffu, ps1, 2);
        l0 = l0 * al0 + ps0;
        l1 = l1 * al1 + ps1;

#pragma unroll
        for (int t = 0; t < 8; t++) {
            o[t][0] *= al0; o[t][1] *= al0;
            o[t][2] *= al1; o[t][3] *= al1;
        }

#pragma unroll
        for (int kc = 0; kc < 8; kc++) {
            const uint32_t a0 = pack_bf16(s[2 * kc][0],     s[2 * kc][1]);
            const uint32_t a1 = pack_bf16(s[2 * kc][2],     s[2 * kc][3]);
            const uint32_t a2 = pack_bf16(s[2 * kc + 1][0], s[2 * kc + 1][1]);
            const uint32_t a3 = pack_bf16(s[2 * kc + 1][2], s[2 * kc + 1][3]);
#pragma unroll
            for (int t = 0; t < 8; t++) {
                const uint32_t b0 = *(const uint32_t*)&Vs[(t * 8 + lq) * 136 + kc * 16 + 2 * tq];
                const uint32_t b1 = *(const uint32_t*)&Vs[(t * 8 + lq) * 136 + kc * 16 + 8 + 2 * tq];
                mma16(o[t], a0, a1, a2, a3, b0, b1);
            }
        }
        __syncthreads();
    }

    // bf16 output (feeds Wo bf16 GEMM)
    const float i0 = 1.0f / l0;
    const float i1 = 1.0f / l1;
    const int qr = qt * 64 + warp * 16 + lq;
    __nv_bfloat16* O0 = O + (size_t)(b * S_ + qr) * D_ + h * DK_;
    __nv_bfloat16* O1 = O0 + (size_t)8 * D_;
#pragma unroll
    for (int t = 0; t < 8; t++) {
        *(__nv_bfloat162*)(O0 + t * 8 + 2 * tq) = __floats2bfloat162_rn(o[t][0] * i0, o[t][1] * i0);
        *(__nv_bfloat162*)(O1 + t * 8 + 2 * tq) = __floats2bfloat162_rn(o[t][2] * i1, o[t][3] * i1);
    }
}

// ---------------------------------------------------------------------------
// Fused residual add + LayerNorm; optionally writes tf32-rounded copy.
// ---------------------------------------------------------------------------
template <bool WR>
__global__ void __launch_bounds__(256)
ln_residual_kernel(const float* __restrict__ X, const float* __restrict__ R,
                   const float* __restrict__ ga, const float* __restrict__ gb,
                   float* __restrict__ out, float* __restrict__ outr)
{
    const int row = blockIdx.x;
    const int t   = threadIdx.x;
    const float* xr = X + (size_t)row * D_;
    const float* rr = R + (size_t)row * D_;

    float v[3];
#pragma unroll
    for (int i = 0; i < 3; i++) v[i] = xr[t + i * 256] + rr[t + i * 256];

    __shared__ float sbuf[8];

    float s = v[0] + v[1] + v[2];
#pragma unroll
    for (int off = 16; off > 0; off >>= 1) s += __shfl_xor_sync(0xffffffffu, s, off);
    if ((t & 31) == 0) sbuf[t >> 5] = s;
    __syncthreads();
    float tot = 0.f;
#pragma unroll
    for (int i = 0; i < 8; i++) tot += sbuf[i];
    const float mean = tot * (1.0f / (float)D_);
    __syncthreads();

    float d0 = v[0] - mean, d1 = v[1] - mean, d2 = v[2] - mean;
    float sq = d0 * d0 + d1 * d1 + d2 * d2;
#pragma unroll
    for (int off = 16; off > 0; off >>= 1) sq += __shfl_xor_sync(0xffffffffu, sq, off);
    if ((t & 31) == 0) sbuf[t >> 5] = sq;
    __syncthreads();
    float tot2 = 0.f;
#pragma unroll
    for (int i = 0; i < 8; i++) tot2 += sbuf[i];
    const float var = tot2 * (1.0f / (float)(D_ - 1));
    const float inv = 1.0f / (sqrtf(var) + 1e-6f);

    float* orow = out + (size_t)row * D_;
    const float o0 = ga[t      ] * d0 * inv + gb[t      ];
    const float o1 = ga[t + 256] * d1 * inv + gb[t + 256];
    const float o2 = ga[t + 512] * d2 * inv + gb[t + 512];
    orow[t      ] = o0;
    orow[t + 256] = o1;
    orow[t + 512] = o2;
    if (WR) {
        float* orr = outr + (size_t)row * D_;
        orr[t      ] = rf(o0);
        orr[t + 256] = rf(o1);
        orr[t + 512] = rf(o2);
    }
}

// ---------------------------------------------------------------------------
// Launch
// ---------------------------------------------------------------------------
extern "C" void kernel_launch(void* const* d_in, const int* in_sizes, int n_in,
                              void* d_out, int out_size)
{
    const float* x    = (const float*)d_in[0];
    const int*   mask = (const int*)  d_in[1];
    const float* Wq   = (const float*)d_in[2];
    const float* bq   = (const float*)d_in[3];
    const float* Wk   = (const float*)d_in[4];
    const float* bk   = (const float*)d_in[5];
    const float* Wv   = (const float*)d_in[6];
    const float* bv   = (const float*)d_in[7];
    const float* Wo   = (const float*)d_in[8];
    const float* bo   = (const float*)d_in[9];
    const float* W1   = (const float*)d_in[10];
    const float* b1   = (const float*)d_in[11];
    const float* W2   = (const float*)d_in[12];
    const float* b2   = (const float*)d_in[13];
    const float* ln1a = (const float*)d_in[14];
    const float* ln1b = (const float*)d_in[15];
    const float* ln2a = (const float*)d_in[16];
    const float* ln2b = (const float*)d_in[17];

    __nv_bfloat16 *xb, *qb, *kb, *vtb, *att, *ffh;
    __nv_bfloat16 *wqT, *wkT, *wvT, *woT, *w2T;
    float *tmp, *out1, *o1r, *w1T;
    cudaGetSymbolAddress((void**)&xb,   g_xb);
    cudaGetSymbolAddress((void**)&qb,   g_qb);
    cudaGetSymbolAddress((void**)&kb,   g_kb);
    cudaGetSymbolAddress((void**)&vtb,  g_vtb);
    cudaGetSymbolAddress((void**)&att,  g_att);
    cudaGetSymbolAddress((void**)&ffh,  g_ffh);
    cudaGetSymbolAddress((void**)&tmp,  g_tmp);
    cudaGetSymbolAddress((void**)&out1, g_out1);
    cudaGetSymbolAddress((void**)&o1r,  g_o1r);
    cudaGetSymbolAddress((void**)&wqT,  g_wqT);
    cudaGetSymbolAddress((void**)&wkT,  g_wkT);
    cudaGetSymbolAddress((void**)&wvT,  g_wvT);
    cudaGetSymbolAddress((void**)&woT,  g_woT);
    cudaGetSymbolAddress((void**)&w1T,  g_w1T);
    cudaGetSymbolAddress((void**)&w2T,  g_w2T);

    cudaFuncSetAttribute(mma_gemm_t<5>, cudaFuncAttributeMaxDynamicSharedMemorySize, GEMM_SMEM);
    cudaFuncSetAttribute(mma_gemm_b<0>, cudaFuncAttributeMaxDynamicSharedMemorySize, GEMM_SMEM);
    cudaFuncSetAttribute(mma_gemm_b<4>, cudaFuncAttributeMaxDynamicSharedMemorySize, GEMM_SMEM);
    cudaFuncSetAttribute(mma_gemm_b_qk, cudaFuncAttributeMaxDynamicSharedMemorySize, GEMM_SMEM);

    // x -> bf16
    round_xb_kernel<<<(M_ * D_) / 4 / 256, 256>>>((const float4*)x, (uint2*)xb);

    // Weight transposes
    dim3 tb(32, 8);
    transpose_qkvo<<<dim3(D_ / 32, D_ / 32, 4), tb>>>(Wq, Wk, Wv, Wo, wqT, wkT, wvT, woT);
    transpose_tf32<<<dim3(D_ / 32, F_ / 32), tb>>>(W1, w1T, D_, F_);
    transpose_b16<<<dim3(F_ / 32, D_ / 32), tb>>>(W2, w2T, F_, D_);

    dim3 gProj(D_ / 128, M_ / 128);          // (6, 64)
    dim3 gQk  (D_ / 128, M_ / 128, 2);       // (6, 64, 2)
    dim3 gFfn1(F_ / 128, M_ / 128);          // (24, 64)

    // Q,K projections (bf16, head-split) + V projection (bf16, transposed)
    mma_gemm_b_qk<<<gQk, 128, GEMM_SMEM>>>(xb, wqT, wkT, bq, bk, qb, kb);
    mma_gemm_b<4><<<gProj, 128, GEMM_SMEM>>>(xb, wvT, bv, vtb, D_, D_);

    // Attention (bf16 tensor cores, bf16 output)
    dim3 gAttn(S_ / 64, H_, B_);
    flash_attn_bf16<<<gAttn, 128>>>(qb, kb, vtb, mask, att);

    // Output projection (bf16)
    mma_gemm_b<0><<<gProj, 128, GEMM_SMEM>>>(att, woT, bo, tmp, D_, D_);

    // LN1(x + attn_out) -> out1 (fp32) + o1r (tf32, FFN1 A-operand)
    ln_residual_kernel<true><<<M_, 256>>>(x, tmp, ln1a, ln1b, out1, o1r);

    // FFN1 (tf32, gelu -> bf16) ; FFN2 (bf16)
    mma_gemm_t<5><<<gFfn1, 128, GEMM_SMEM>>>(o1r, w1T, b1, ffh, F_, D_);
    mma_gemm_b<0><<<gProj, 128, GEMM_SMEM>>>(ffh, w2T, b2, tmp, D_, F_);

    // LN2(out1 + ffn) -> output
    ln_residual_kernel<false><<<M_, 256>>>(out1, tmp, ln2a, ln2b, (float*)d_out, nullptr);
}

// round 7
// speedup vs baseline: 6.0112x; 1.1730x over previous
#include <cuda_runtime.h>
#include <cuda_fp16.h>
#include <math.h>
#include <stdint.h>

// ---------------------------------------------------------------------------
// Problem constants
// ---------------------------------------------------------------------------
#define B_   8
#define S_   1024
#define D_   768
#define F_   3072
#define H_   12
#define DK_  64
#define M_   (B_ * S_)       // 8192 rows

// ---------------------------------------------------------------------------
// Scratch (device globals; no allocation allowed)
// ---------------------------------------------------------------------------
__device__ __align__(16) __half g_xh [M_ * D_];              // x fp16
__device__ __align__(16) __half g_qh [B_ * H_ * S_ * DK_];   // [B,H,S,dk]
__device__ __align__(16) __half g_kh [B_ * H_ * S_ * DK_];   // [B,H,S,dk]
__device__ __align__(16) __half g_vth[B_ * H_ * DK_ * S_];   // [B,H,dk,S]
__device__ __align__(16) __half g_att[M_ * D_];              // attn out fp16
__device__ __align__(16) __half g_ffh[M_ * F_];              // gelu out fp16
__device__ __align__(16) __half g_o1h[M_ * D_];              // LN1 out fp16
__device__ __align__(16) float g_tmp [M_ * D_];              // fp32 scratch
__device__ __align__(16) float g_out1[M_ * D_];              // LN1 out fp32
// transposed weights, [N, K] K-major, fp16
__device__ __align__(16) __half g_wqT[D_ * D_];
__device__ __align__(16) __half g_wkT[D_ * D_];
__device__ __align__(16) __half g_wvT[D_ * D_];
__device__ __align__(16) __half g_woT[D_ * D_];
__device__ __align__(16) __half g_w1T[F_ * D_];
__device__ __align__(16) __half g_w2T[D_ * F_];

// ---------------------------------------------------------------------------
// Helpers
// ---------------------------------------------------------------------------
__device__ __forceinline__ uint32_t smem_u32(const void* p) {
    uint32_t a;
    asm("{ .reg .u64 t; cvta.to.shared.u64 t, %1; cvt.u32.u64 %0, t; }"
        : "=r"(a) : "l"(p));
    return a;
}

__device__ __forceinline__ void cp16(uint32_t dst, const void* src) {
    asm volatile("cp.async.cg.shared.global [%0], [%1], 16;"
                 :: "r"(dst), "l"(src) : "memory");
}
#define CP_COMMIT asm volatile("cp.async.commit_group;" ::: "memory")
#define CP_WAIT2  asm volatile("cp.async.wait_group 2;" ::: "memory")

// m16n8k16 FP16 MMA (fp32 accumulate)
__device__ __forceinline__ void mma16(float* c,
                                      uint32_t a0, uint32_t a1, uint32_t a2, uint32_t a3,
                                      uint32_t b0, uint32_t b1)
{
    asm volatile(
        "mma.sync.aligned.m16n8k16.row.col.f32.f16.f16.f32 "
        "{%0,%1,%2,%3}, {%4,%5,%6,%7}, {%8,%9}, {%0,%1,%2,%3};"
        : "+f"(c[0]), "+f"(c[1]), "+f"(c[2]), "+f"(c[3])
        : "r"(a0), "r"(a1), "r"(a2), "r"(a3), "r"(b0), "r"(b1));
}

// pack two fp32 -> f16x2 (lo = first arg)
__device__ __forceinline__ uint32_t pack_f16(float lo, float hi) {
    uint32_t r;
    asm("cvt.rn.f16x2.f32 %0, %1, %2;" : "=r"(r) : "f"(hi), "f"(lo));
    return r;
}

__device__ __forceinline__ float gelu_t(float x) {
    const float c = 0.7978845608028654f;
    float t = tanhf(c * (x + 0.044715f * x * x * x));
    return 0.5f * x * (1.0f + t);
}

// ---------------------------------------------------------------------------
// x -> fp16 copy
// ---------------------------------------------------------------------------
__global__ void __launch_bounds__(256)
round_xh_kernel(const float4* __restrict__ in, uint2* __restrict__ out)
{
    const int i = blockIdx.x * 256 + threadIdx.x;
    float4 v = in[i];
    uint2 o;
    o.x = pack_f16(v.x, v.y);
    o.y = pack_f16(v.z, v.w);
    out[i] = o;
}

// ---------------------------------------------------------------------------
// Weight transposes W[K,N] -> Wt[N,K], fp16 output
// ---------------------------------------------------------------------------
__device__ __forceinline__ void transpose_body_f16(
    const float* __restrict__ W, __half* __restrict__ Wt, int K, int N)
{
    __shared__ float t[32][33];
    const int k0 = blockIdx.x * 32;
    const int n0 = blockIdx.y * 32;
    const int x = threadIdx.x;
    const int y = threadIdx.y;
#pragma unroll
    for (int i = 0; i < 32; i += 8)
        t[y + i][x] = W[(size_t)(k0 + y + i) * N + n0 + x];
    __syncthreads();
#pragma unroll
    for (int i = 0; i < 32; i += 8)
        Wt[(size_t)(n0 + y + i) * K + k0 + x] = __float2half_rn(t[x][y + i]);
}

__global__ void __launch_bounds__(256)
transpose_f16(const float* __restrict__ W, __half* __restrict__ Wt, int K, int N)
{
    transpose_body_f16(W, Wt, K, N);
}

__global__ void __launch_bounds__(256)
transpose_qkvo(const float* __restrict__ Wq, const float* __restrict__ Wk,
               const float* __restrict__ Wv, const float* __restrict__ Wo,
               __half* __restrict__ oq, __half* __restrict__ ok,
               __half* __restrict__ ov, __half* __restrict__ oo)
{
    const float* W; __half* Wt;
    if (blockIdx.z == 0)      { W = Wq; Wt = oq; }
    else if (blockIdx.z == 1) { W = Wk; Wt = ok; }
    else if (blockIdx.z == 2) { W = Wv; Wt = ov; }
    else                      { W = Wo; Wt = oo; }
    transpose_body_f16(W, Wt, D_, D_);
}

// ---------------------------------------------------------------------------
// Shared epilogue (fp32 accumulators -> various output formats)
//   EPI: 0 plain fp32, 3 fp16 head-split [B,H,S,dk],
//        4 fp16 transposed head-split [B,H,dk,S], 5 gelu -> fp16 row-major
// ---------------------------------------------------------------------------
template <int EPI>
__device__ __forceinline__ void epilogue(
    float acc[4][8][4], const float* __restrict__ bias, void* __restrict__ C,
    int N, int m0, int n0, int wm, int wn, int lq, int tq)
{
#pragma unroll
    for (int mi = 0; mi < 4; mi++) {
        const int r0 = m0 + wm + mi * 16 + lq;
#pragma unroll
        for (int ni = 0; ni < 8; ni++) {
            const int c0 = n0 + wn + ni * 8 + 2 * tq;
            const float bv0 = bias[c0];
            const float bv1 = bias[c0 + 1];
            float v00 = acc[mi][ni][0] + bv0;
            float v01 = acc[mi][ni][1] + bv1;
            float v10 = acc[mi][ni][2] + bv0;
            float v11 = acc[mi][ni][3] + bv1;
            if (EPI == 5) {
                v00 = gelu_t(v00); v01 = gelu_t(v01);
                v10 = gelu_t(v10); v11 = gelu_t(v11);
            }
            if (EPI == 3) {
                __half* Ch = (__half*)C;
                const int hh = c0 >> 6, dd = c0 & 63;
                {
                    const int bb = r0 >> 10, ss = r0 & 1023;
                    *(__half2*)&Ch[(size_t)((bb * H_ + hh) * S_ + ss) * DK_ + dd] =
                        __floats2half2_rn(v00, v01);
                }
                {
                    const int r1 = r0 + 8;
                    const int bb = r1 >> 10, ss = r1 & 1023;
                    *(__half2*)&Ch[(size_t)((bb * H_ + hh) * S_ + ss) * DK_ + dd] =
                        __floats2half2_rn(v10, v11);
                }
            } else if (EPI == 4) {
                __half* Ch = (__half*)C;
                const int hh = c0 >> 6, dd = c0 & 63;
                const int bb = r0 >> 10, ss = r0 & 1023;
                const size_t base = (size_t)((bb * H_ + hh) * DK_ + dd) * S_ + ss;
                Ch[base]           = __float2half_rn(v00);
                Ch[base + S_]      = __float2half_rn(v01);
                Ch[base + 8]       = __float2half_rn(v10);
                Ch[base + S_ + 8]  = __float2half_rn(v11);
            } else if (EPI == 5) {
                __half* Ch = (__half*)C;
                *(__half2*)&Ch[(size_t)r0 * N + c0]       = __floats2half2_rn(v00, v01);
                *(__half2*)&Ch[(size_t)(r0 + 8) * N + c0] = __floats2half2_rn(v10, v11);
            } else {
                float* Cf = (float*)C;
                *(float2*)&Cf[(size_t)r0 * N + c0]       = make_float2(v00, v01);
                *(float2*)&Cf[(size_t)(r0 + 8) * N + c0] = make_float2(v10, v11);
            }
        }
    }
}

// ---------------------------------------------------------------------------
// FP16 mma.sync GEMM, cp.async 3-stage pipeline.
//   C[M,N] = A[M,K] @ Bt[N,K]^T + bias
//   CTA 128x128, 128 threads (4 warps 2x2), warp tile 64x64, BK=64.
//   Smem: 128 rows x 72 halves per operand stage (stride-72 conflict-free).
// ---------------------------------------------------------------------------
#define HST   72                     // halves per row
#define HSTGH (128 * HST)            // halves per stage = 9216
#define HSTGB (HSTGH * 2)            // 18432 bytes
#define GEMM_SMEM (6 * HSTGB)        // 110592

template <int EPI>
__device__ __forceinline__ void gemm_f16_body(
    const __half* __restrict__ A, const __half* __restrict__ Bt,
    const float* __restrict__ bias, void* __restrict__ C,
    int N, int K, int m0, int n0)
{
    extern __shared__ __half smh[];
    const uint32_t sbase = smem_u32(smh);

    const int tid  = threadIdx.x;
    const int warp = tid >> 5;
    const int lane = tid & 31;
    const int wm = (warp >> 1) * 64;
    const int wn = (warp & 1) * 64;
    const int lq = lane >> 2;
    const int tq = lane & 3;

    const int rr  = tid >> 3;            // 0..15
    const int cc8 = (tid & 7) * 8;       // halves, 0..56

    const __half* Ap = A  + (size_t)(m0 + rr) * K + cc8;
    const __half* Bp = Bt + (size_t)(n0 + rr) * K + cc8;
    const uint32_t dA = sbase + (uint32_t)(rr * HST + cc8) * 2;
    const uint32_t dB = dA + 3 * HSTGB;

    const int KIT = K >> 6;

    float acc[4][8][4];
#pragma unroll
    for (int mi = 0; mi < 4; mi++)
#pragma unroll
        for (int ni = 0; ni < 8; ni++)
#pragma unroll
            for (int j = 0; j < 4; j++) acc[mi][ni][j] = 0.0f;

    auto issue = [&](int it) {
        if (it < KIT) {
            const __half* a = Ap + it * 64;
            const __half* b = Bp + it * 64;
            const uint32_t off = (uint32_t)(it % 3) * HSTGB;
#pragma unroll
            for (int i = 0; i < 8; i++) {
                cp16(dA + off + (uint32_t)(i * 16 * HST) * 2, a + (size_t)(i * 16) * K);
                cp16(dB + off + (uint32_t)(i * 16 * HST) * 2, b + (size_t)(i * 16) * K);
            }
        }
        CP_COMMIT;
    };

    issue(0); issue(1); issue(2);

    for (int it = 0; it < KIT; ++it) {
        CP_WAIT2;
        __syncthreads();
        const __half* As = smh + (it % 3) * HSTGH;
        const __half* Bs = As + 3 * HSTGH;

#pragma unroll
        for (int s = 0; s < 4; ++s) {     // 4 x k16
            uint32_t bf[8][2];
#pragma unroll
            for (int ni = 0; ni < 8; ni++) {
                const int bb = (wn + ni * 8 + lq) * HST + s * 16 + 2 * tq;
                bf[ni][0] = *(const uint32_t*)&Bs[bb];
                bf[ni][1] = *(const uint32_t*)&Bs[bb + 8];
            }
#pragma unroll
            for (int mi = 0; mi < 4; mi++) {
                const int ab = (wm + mi * 16 + lq) * HST + s * 16 + 2 * tq;
                const uint32_t a0 = *(const uint32_t*)&As[ab];
                const uint32_t a1 = *(const uint32_t*)&As[ab + 8 * HST];
                const uint32_t a2 = *(const uint32_t*)&As[ab + 8];
                const uint32_t a3 = *(const uint32_t*)&As[ab + 8 * HST + 8];
#pragma unroll
                for (int ni = 0; ni < 8; ni++)
                    mma16(acc[mi][ni], a0, a1, a2, a3, bf[ni][0], bf[ni][1]);
            }
        }
        __syncthreads();
        issue(it + 3);
    }

    epilogue<EPI>(acc, bias, C, N, m0, n0, wm, wn, lq, tq);
}

template <int EPI>
__global__ void __launch_bounds__(128)
mma_gemm_h(const __half* __restrict__ A, const __half* __restrict__ Bt,
           const float* __restrict__ bias, void* __restrict__ C,
           int N, int K)
{
    gemm_f16_body<EPI>(A, Bt, bias, C, N, K, blockIdx.y * 128, blockIdx.x * 128);
}

// Q/K projections fused (z = 0/1), fp16 head-split output
__global__ void __launch_bounds__(128)
mma_gemm_h_qk(const __half* __restrict__ A,
              const __half* __restrict__ wq, const __half* __restrict__ wk,
              const float* __restrict__ bq, const float* __restrict__ bk,
              __half* __restrict__ oq, __half* __restrict__ ok)
{
    const __half* Bt = blockIdx.z == 0 ? wq : wk;
    const float* bia = blockIdx.z == 0 ? bq : bk;
    __half* C        = blockIdx.z == 0 ? oq : ok;
    gemm_f16_body<3>(A, Bt, bia, C, D_, D_, blockIdx.y * 128, blockIdx.x * 128);
}

// ---------------------------------------------------------------------------
// FP16 tensor-core flash attention; output stored fp16 [B,S,D].
// Block = 128 threads (4 warps), each warp owns 16 query rows -> 64 q/CTA.
// ---------------------------------------------------------------------------
__global__ void __launch_bounds__(128)
flash_attn_f16(const __half* __restrict__ Q,
               const __half* __restrict__ K,
               const __half* __restrict__ Vt,
               const int* __restrict__ mask,
               __half* __restrict__ O)
{
    const int qt = blockIdx.x;
    const int h  = blockIdx.y;
    const int b  = blockIdx.z;
    const int tid  = threadIdx.x;
    const int warp = tid >> 5;
    const int lane = tid & 31;
    const int lq = lane >> 2;
    const int tq = lane & 3;
    const int bh = b * H_ + h;

    __shared__ __half Ks[128 * 72];
    __shared__ __half Vs[64 * 136];
    __shared__ int mk[128];

    {
        const __half* Qb = Q + (size_t)(bh * S_ + qt * 64) * DK_;
        const int r = tid >> 1, hf = tid & 1;
        const uint4* src = (const uint4*)(Qb + r * DK_ + hf * 32);
        uint4* dst = (uint4*)&Ks[r * 72 + hf * 32];
#pragma unroll
        for (int i = 0; i < 4; i++) dst[i] = src[i];
    }
    __syncthreads();
    uint32_t qa[4][4];
    {
        const int r0 = warp * 16 + lq;
#pragma unroll
        for (int ks = 0; ks < 4; ks++) {
            qa[ks][0] = *(const uint32_t*)&Ks[(r0    ) * 72 + ks * 16 + 2 * tq];
            qa[ks][1] = *(const uint32_t*)&Ks[(r0 + 8) * 72 + ks * 16 + 2 * tq];
            qa[ks][2] = *(const uint32_t*)&Ks[(r0    ) * 72 + ks * 16 + 8 + 2 * tq];
            qa[ks][3] = *(const uint32_t*)&Ks[(r0 + 8) * 72 + ks * 16 + 8 + 2 * tq];
        }
    }
    __syncthreads();

    float o[8][4];
#pragma unroll
    for (int t = 0; t < 8; t++)
#pragma unroll
        for (int j = 0; j < 4; j++) o[t][j] = 0.0f;
    float m0 = -1e30f, m1 = -1e30f, l0 = 0.0f, l1 = 0.0f;

    const __half* Kb = K  + (size_t)bh * S_ * DK_;
    const __half* Vb = Vt + (size_t)bh * DK_ * S_;

    for (int kt = 0; kt < 8; kt++) {
        {
            const uint4* src = (const uint4*)(Kb + (size_t)(kt * 128 + tid) * DK_);
            uint4* dst = (uint4*)&Ks[tid * 72];
#pragma unroll
            for (int i = 0; i < 8; i++) dst[i] = src[i];
        }
        {
            const int r = tid >> 1, hf = tid & 1;
            const uint4* src = (const uint4*)(Vb + (size_t)r * S_ + kt * 128 + hf * 64);
            uint4* dst = (uint4*)&Vs[r * 136 + hf * 64];
#pragma unroll
            for (int i = 0; i < 8; i++) dst[i] = src[i];
        }
        mk[tid] = mask[b * S_ + kt * 128 + tid];
        __syncthreads();

        float s[16][4];
#pragma unroll
        for (int nt = 0; nt < 16; nt++) {
            s[nt][0] = s[nt][1] = s[nt][2] = s[nt][3] = 0.0f;
#pragma unroll
            for (int ks = 0; ks < 4; ks++) {
                const uint32_t b0 = *(const uint32_t*)&Ks[(nt * 8 + lq) * 72 + ks * 16 + 2 * tq];
                const uint32_t b1 = *(const uint32_t*)&Ks[(nt * 8 + lq) * 72 + ks * 16 + 8 + 2 * tq];
                mma16(s[nt], qa[ks][0], qa[ks][1], qa[ks][2], qa[ks][3], b0, b1);
            }
        }

        float mx0 = -1e30f, mx1 = -1e30f;
#pragma unroll
        for (int nt = 0; nt < 16; nt++) {
            const int c = nt * 8 + 2 * tq;
            const bool k0 = mk[c] != 0, k1 = mk[c + 1] != 0;
            s[nt][0] = k0 ? s[nt][0] * 0.125f : -1e9f;
            s[nt][1] = k1 ? s[nt][1] * 0.125f : -1e9f;
            s[nt][2] = k0 ? s[nt][2] * 0.125f : -1e9f;
            s[nt][3] = k1 ? s[nt][3] * 0.125f : -1e9f;
            mx0 = fmaxf(mx0, fmaxf(s[nt][0], s[nt][1]));
            mx1 = fmaxf(mx1, fmaxf(s[nt][2], s[nt][3]));
        }
        mx0 = fmaxf(mx0, __shfl_xor_sync(0xffffffffu, mx0, 1));
        mx0 = fmaxf(mx0, __shfl_xor_sync(0xffffffffu, mx0, 2));
        mx1 = fmaxf(mx1, __shfl_xor_sync(0xffffffffu, mx1, 1));
        mx1 = fmaxf(mx1, __shfl_xor_sync(0xffffffffu, mx1, 2));

        const float nm0 = fmaxf(m0, mx0);
        const float nm1 = fmaxf(m1, mx1);
        const float al0 = __expf(m0 - nm0);
        const float al1 = __expf(m1 - nm1);
        m0 = nm0; m1 = nm1;

        float ps0 = 0.0f, ps1 = 0.0f;
#pragma unroll
        for (int nt = 0; nt < 16; nt++) {
            s[nt][0] = __expf(s[nt][0] - m0);
            s[nt][1] = __expf(s[nt][1] - m0);
            s[nt][2] = __expf(s[nt][2] - m1);
            s[nt][3] = __expf(s[nt][3] - m1);
            ps0 += s[nt][0] + s[nt][1];
            ps1 += s[nt][2] + s[nt][3];
        }
        ps0 += __shfl_xor_sync(0xffffffffu, ps0, 1);
        ps0 += __shfl_xor_sync(0xffffffffu, ps0, 2);
        ps1 += __shfl_xor_sync(0xffffffffu, ps1, 1);
        ps1 += __shfl_xor_sync(0xffffffffu, ps1, 2);
        l0 = l0 * al0 + ps0;
        l1 = l1 * al1 + ps1;

#pragma unroll
        for (int t = 0; t < 8; t++) {
            o[t][0] *= al0; o[t][1] *= al0;
            o[t][2] *= al1; o[t][3] *= al1;
        }

#pragma unroll
        for (int kc = 0; kc < 8; kc++) {
            const uint32_t a0 = pack_f16(s[2 * kc][0],     s[2 * kc][1]);
            const uint32_t a1 = pack_f16(s[2 * kc][2],     s[2 * kc][3]);
            const uint32_t a2 = pack_f16(s[2 * kc + 1][0], s[2 * kc + 1][1]);
            const uint32_t a3 = pack_f16(s[2 * kc + 1][2], s[2 * kc + 1][3]);
#pragma unroll
            for (int t = 0; t < 8; t++) {
                const uint32_t b0 = *(const uint32_t*)&Vs[(t * 8 + lq) * 136 + kc * 16 + 2 * tq];
                const uint32_t b1 = *(const uint32_t*)&Vs[(t * 8 + lq) * 136 + kc * 16 + 8 + 2 * tq];
                mma16(o[t], a0, a1, a2, a3, b0, b1);
            }
        }
        __syncthreads();
    }

    // fp16 output (feeds Wo fp16 GEMM)
    const float i0 = 1.0f / l0;
    const float i1 = 1.0f / l1;
    const int qr = qt * 64 + warp * 16 + lq;
    __half* O0 = O + (size_t)(b * S_ + qr) * D_ + h * DK_;
    __half* O1 = O0 + (size_t)8 * D_;
#pragma unroll
    for (int t = 0; t < 8; t++) {
        *(__half2*)(O0 + t * 8 + 2 * tq) = __floats2half2_rn(o[t][0] * i0, o[t][1] * i0);
        *(__half2*)(O1 + t * 8 + 2 * tq) = __floats2half2_rn(o[t][2] * i1, o[t][3] * i1);
    }
}

// ---------------------------------------------------------------------------
// Fused residual add + LayerNorm; optionally writes fp16 copy.
// ---------------------------------------------------------------------------
template <bool WH>
__global__ void __launch_bounds__(256)
ln_residual_kernel(const float* __restrict__ X, const float* __restrict__ R,
                   const float* __restrict__ ga, const float* __restrict__ gb,
                   float* __restrict__ out, __half* __restrict__ outh)
{
    const int row = blockIdx.x;
    const int t   = threadIdx.x;
    const float* xr = X + (size_t)row * D_;
    const float* rr = R + (size_t)row * D_;

    float v[3];
#pragma unroll
    for (int i = 0; i < 3; i++) v[i] = xr[t + i * 256] + rr[t + i * 256];

    __shared__ float sbuf[8];

    float s = v[0] + v[1] + v[2];
#pragma unroll
    for (int off = 16; off > 0; off >>= 1) s += __shfl_xor_sync(0xffffffffu, s, off);
    if ((t & 31) == 0) sbuf[t >> 5] = s;
    __syncthreads();
    float tot = 0.f;
#pragma unroll
    for (int i = 0; i < 8; i++) tot += sbuf[i];
    const float mean = tot * (1.0f / (float)D_);
    __syncthreads();

    float d0 = v[0] - mean, d1 = v[1] - mean, d2 = v[2] - mean;
    float sq = d0 * d0 + d1 * d1 + d2 * d2;
#pragma unroll
    for (int off = 16; off > 0; off >>= 1) sq += __shfl_xor_sync(0xffffffffu, sq, off);
    if ((t & 31) == 0) sbuf[t >> 5] = sq;
    __syncthreads();
    float tot2 = 0.f;
#pragma unroll
    for (int i = 0; i < 8; i++) tot2 += sbuf[i];
    const float var = tot2 * (1.0f / (float)(D_ - 1));
    const float inv = 1.0f / (sqrtf(var) + 1e-6f);

    float* orow = out + (size_t)row * D_;
    const float o0 = ga[t      ] * d0 * inv + gb[t      ];
    const float o1 = ga[t + 256] * d1 * inv + gb[t + 256];
    const float o2 = ga[t + 512] * d2 * inv + gb[t + 512];
    orow[t      ] = o0;
    orow[t + 256] = o1;
    orow[t + 512] = o2;
    if (WH) {
        __half* orh = outh + (size_t)row * D_;
        orh[t      ] = __float2half_rn(o0);
        orh[t + 256] = __float2half_rn(o1);
        orh[t + 512] = __float2half_rn(o2);
    }
}

// ---------------------------------------------------------------------------
// Launch
// ---------------------------------------------------------------------------
extern "C" void kernel_launch(void* const* d_in, const int* in_sizes, int n_in,
                              void* d_out, int out_size)
{
    const float* x    = (const float*)d_in[0];
    const int*   mask = (const int*)  d_in[1];
    const float* Wq   = (const float*)d_in[2];
    const float* bq   = (const float*)d_in[3];
    const float* Wk   = (const float*)d_in[4];
    const float* bk   = (const float*)d_in[5];
    const float* Wv   = (const float*)d_in[6];
    const float* bv   = (const float*)d_in[7];
    const float* Wo   = (const float*)d_in[8];
    const float* bo   = (const float*)d_in[9];
    const float* W1   = (const float*)d_in[10];
    const float* b1   = (const float*)d_in[11];
    const float* W2   = (const float*)d_in[12];
    const float* b2   = (const float*)d_in[13];
    const float* ln1a = (const float*)d_in[14];
    const float* ln1b = (const float*)d_in[15];
    const float* ln2a = (const float*)d_in[16];
    const float* ln2b = (const float*)d_in[17];

    __half *xh, *qh, *kh, *vth, *att, *ffh, *o1h;
    __half *wqT, *wkT, *wvT, *woT, *w1T, *w2T;
    float *tmp, *out1;
    cudaGetSymbolAddress((void**)&xh,   g_xh);
    cudaGetSymbolAddress((void**)&qh,   g_qh);
    cudaGetSymbolAddress((void**)&kh,   g_kh);
    cudaGetSymbolAddress((void**)&vth,  g_vth);
    cudaGetSymbolAddress((void**)&att,  g_att);
    cudaGetSymbolAddress((void**)&ffh,  g_ffh);
    cudaGetSymbolAddress((void**)&o1h,  g_o1h);
    cudaGetSymbolAddress((void**)&tmp,  g_tmp);
    cudaGetSymbolAddress((void**)&out1, g_out1);
    cudaGetSymbolAddress((void**)&wqT,  g_wqT);
    cudaGetSymbolAddress((void**)&wkT,  g_wkT);
    cudaGetSymbolAddress((void**)&wvT,  g_wvT);
    cudaGetSymbolAddress((void**)&woT,  g_woT);
    cudaGetSymbolAddress((void**)&w1T,  g_w1T);
    cudaGetSymbolAddress((void**)&w2T,  g_w2T);

    cudaFuncSetAttribute(mma_gemm_h<0>, cudaFuncAttributeMaxDynamicSharedMemorySize, GEMM_SMEM);
    cudaFuncSetAttribute(mma_gemm_h<4>, cudaFuncAttributeMaxDynamicSharedMemorySize, GEMM_SMEM);
    cudaFuncSetAttribute(mma_gemm_h<5>, cudaFuncAttributeMaxDynamicSharedMemorySize, GEMM_SMEM);
    cudaFuncSetAttribute(mma_gemm_h_qk, cudaFuncAttributeMaxDynamicSharedMemorySize, GEMM_SMEM);

    // x -> fp16
    round_xh_kernel<<<(M_ * D_) / 4 / 256, 256>>>((const float4*)x, (uint2*)xh);

    // Weight transposes
    dim3 tb(32, 8);
    transpose_qkvo<<<dim3(D_ / 32, D_ / 32, 4), tb>>>(Wq, Wk, Wv, Wo, wqT, wkT, wvT, woT);
    transpose_f16<<<dim3(D_ / 32, F_ / 32), tb>>>(W1, w1T, D_, F_);
    transpose_f16<<<dim3(F_ / 32, D_ / 32), tb>>>(W2, w2T, F_, D_);

    dim3 gProj(D_ / 128, M_ / 128);          // (6, 64)
    dim3 gQk  (D_ / 128, M_ / 128, 2);       // (6, 64, 2)
    dim3 gFfn1(F_ / 128, M_ / 128);          // (24, 64)

    // Q,K projections (fp16, head-split) + V projection (fp16, transposed)
    mma_gemm_h_qk<<<gQk, 128, GEMM_SMEM>>>(xh, wqT, wkT, bq, bk, qh, kh);
    mma_gemm_h<4><<<gProj, 128, GEMM_SMEM>>>(xh, wvT, bv, vth, D_, D_);

    // Attention (fp16 tensor cores, fp16 output)
    dim3 gAttn(S_ / 64, H_, B_);
    flash_attn_f16<<<gAttn, 128>>>(qh, kh, vth, mask, att);

    // Output projection (fp16)
    mma_gemm_h<0><<<gProj, 128, GEMM_SMEM>>>(att, woT, bo, tmp, D_, D_);

    // LN1(x + attn_out) -> out1 (fp32) + o1h (fp16, FFN1 A-operand)
    ln_residual_kernel<true><<<M_, 256>>>(x, tmp, ln1a, ln1b, out1, o1h);

    // FFN1 (fp16, gelu -> fp16) ; FFN2 (fp16)
    mma_gemm_h<5><<<gFfn1, 128, GEMM_SMEM>>>(o1h, w1T, b1, ffh, F_, D_);
    mma_gemm_h<0><<<gProj, 128, GEMM_SMEM>>>(ffh, w2T, b2, tmp, D_, F_);

    // LN2(out1 + ffn) -> output
    ln_residual_kernel<false><<<M_, 256>>>(out1, tmp, ln2a, ln2b, (float*)d_out, nullptr);
}

// round 8
// speedup vs baseline: 6.3056x; 1.0490x over previous
#include <cuda_runtime.h>
#include <cuda_fp16.h>
#include <math.h>
#include <stdint.h>

// ---------------------------------------------------------------------------
// Problem constants
// ---------------------------------------------------------------------------
#define B_   8
#define S_   1024
#define D_   768
#define F_   3072
#define H_   12
#define DK_  64
#define M_   (B_ * S_)       // 8192 rows

// ---------------------------------------------------------------------------
// Scratch (device globals; no allocation allowed)
// ---------------------------------------------------------------------------
__device__ __align__(16) __half g_xh [M_ * D_];              // x fp16
__device__ __align__(16) __half g_qh [B_ * H_ * S_ * DK_];   // [B,H,S,dk]
__device__ __align__(16) __half g_kh [B_ * H_ * S_ * DK_];   // [B,H,S,dk]
__device__ __align__(16) __half g_vth[B_ * H_ * DK_ * S_];   // [B,H,dk,S]
__device__ __align__(16) __half g_att[M_ * D_];              // attn out fp16
__device__ __align__(16) __half g_ffh[M_ * F_];              // gelu out fp16
__device__ __align__(16) __half g_o1h[M_ * D_];              // LN1 out fp16
__device__ __align__(16) float g_tmp [M_ * D_];              // fp32 scratch
__device__ __align__(16) float g_out1[M_ * D_];              // LN1 out fp32
// transposed weights, [N, K] K-major, fp16. QKV concatenated: rows 0..767 = Wq^T,
// 768..1535 = Wk^T, 1536..2303 = Wv^T.
__device__ __align__(16) __half g_wqkvT[3 * D_ * D_];
__device__ __align__(16) __half g_woT[D_ * D_];
__device__ __align__(16) __half g_w1T[F_ * D_];
__device__ __align__(16) __half g_w2T[D_ * F_];

// ---------------------------------------------------------------------------
// Helpers
// ---------------------------------------------------------------------------
__device__ __forceinline__ uint32_t smem_u32(const void* p) {
    uint32_t a;
    asm("{ .reg .u64 t; cvta.to.shared.u64 t, %1; cvt.u32.u64 %0, t; }"
        : "=r"(a) : "l"(p));
    return a;
}

__device__ __forceinline__ void cp16(uint32_t dst, const void* src) {
    asm volatile("cp.async.cg.shared.global [%0], [%1], 16;"
                 :: "r"(dst), "l"(src) : "memory");
}
#define CP_COMMIT asm volatile("cp.async.commit_group;" ::: "memory")
#define CP_WAIT1  asm volatile("cp.async.wait_group 1;" ::: "memory")

// m16n8k16 FP16 MMA (fp32 accumulate)
__device__ __forceinline__ void mma16(float* c,
                                      uint32_t a0, uint32_t a1, uint32_t a2, uint32_t a3,
                                      uint32_t b0, uint32_t b1)
{
    asm volatile(
        "mma.sync.aligned.m16n8k16.row.col.f32.f16.f16.f32 "
        "{%0,%1,%2,%3}, {%4,%5,%6,%7}, {%8,%9}, {%0,%1,%2,%3};"
        : "+f"(c[0]), "+f"(c[1]), "+f"(c[2]), "+f"(c[3])
        : "r"(a0), "r"(a1), "r"(a2), "r"(a3), "r"(b0), "r"(b1));
}

// pack two fp32 -> f16x2 (lo = first arg)
__device__ __forceinline__ uint32_t pack_f16(float lo, float hi) {
    uint32_t r;
    asm("cvt.rn.f16x2.f32 %0, %1, %2;" : "=r"(r) : "f"(hi), "f"(lo));
    return r;
}

__device__ __forceinline__ float gelu_t(float x) {
    const float c = 0.7978845608028654f;
    float t = tanhf(c * (x + 0.044715f * x * x * x));
    return 0.5f * x * (1.0f + t);
}

// ---------------------------------------------------------------------------
// x -> fp16 copy
// ---------------------------------------------------------------------------
__global__ void __launch_bounds__(256)
round_xh_kernel(const float4* __restrict__ in, uint2* __restrict__ out)
{
    const int i = blockIdx.x * 256 + threadIdx.x;
    float4 v = in[i];
    uint2 o;
    o.x = pack_f16(v.x, v.y);
    o.y = pack_f16(v.z, v.w);
    out[i] = o;
}

// ---------------------------------------------------------------------------
// Weight transposes W[K,N] -> Wt[N,K], fp16 output
// ---------------------------------------------------------------------------
__device__ __forceinline__ void transpose_body_f16(
    const float* __restrict__ W, __half* __restrict__ Wt, int K, int N)
{
    __shared__ float t[32][33];
    const int k0 = blockIdx.x * 32;
    const int n0 = blockIdx.y * 32;
    const int x = threadIdx.x;
    const int y = threadIdx.y;
#pragma unroll
    for (int i = 0; i < 32; i += 8)
        t[y + i][x] = W[(size_t)(k0 + y + i) * N + n0 + x];
    __syncthreads();
#pragma unroll
    for (int i = 0; i < 32; i += 8)
        Wt[(size_t)(n0 + y + i) * K + k0 + x] = __float2half_rn(t[x][y + i]);
}

__global__ void __launch_bounds__(256)
transpose_f16(const float* __restrict__ W, __half* __restrict__ Wt, int K, int N)
{
    transpose_body_f16(W, Wt, K, N);
}

__global__ void __launch_bounds__(256)
transpose_qkvo(const float* __restrict__ Wq, const float* __restrict__ Wk,
               const float* __restrict__ Wv, const float* __restrict__ Wo,
               __half* __restrict__ oq, __half* __restrict__ ok,
               __half* __restrict__ ov, __half* __restrict__ oo)
{
    const float* W; __half* Wt;
    if (blockIdx.z == 0)      { W = Wq; Wt = oq; }
    else if (blockIdx.z == 1) { W = Wk; Wt = ok; }
    else if (blockIdx.z == 2) { W = Wv; Wt = ov; }
    else                      { W = Wo; Wt = oo; }
    transpose_body_f16(W, Wt, D_, D_);
}

// ---------------------------------------------------------------------------
// Shared epilogue (fp32 accumulators -> various output formats)
//   EPI: 0 plain fp32, 3 fp16 head-split [B,H,S,dk],
//        4 fp16 transposed head-split [B,H,dk,S], 5 gelu -> fp16 row-major
// ---------------------------------------------------------------------------
template <int EPI>
__device__ __forceinline__ void epilogue(
    float acc[4][8][4], const float* __restrict__ bias, void* __restrict__ C,
    int N, int m0, int n0, int wm, int wn, int lq, int tq)
{
#pragma unroll
    for (int mi = 0; mi < 4; mi++) {
        const int r0 = m0 + wm + mi * 16 + lq;
#pragma unroll
        for (int ni = 0; ni < 8; ni++) {
            const int c0 = n0 + wn + ni * 8 + 2 * tq;
            const float bv0 = bias[c0];
            const float bv1 = bias[c0 + 1];
            float v00 = acc[mi][ni][0] + bv0;
            float v01 = acc[mi][ni][1] + bv1;
            float v10 = acc[mi][ni][2] + bv0;
            float v11 = acc[mi][ni][3] + bv1;
            if (EPI == 5) {
                v00 = gelu_t(v00); v01 = gelu_t(v01);
                v10 = gelu_t(v10); v11 = gelu_t(v11);
            }
            if (EPI == 3) {
                __half* Ch = (__half*)C;
                const int hh = c0 >> 6, dd = c0 & 63;
                {
                    const int bb = r0 >> 10, ss = r0 & 1023;
                    *(__half2*)&Ch[(size_t)((bb * H_ + hh) * S_ + ss) * DK_ + dd] =
                        __floats2half2_rn(v00, v01);
                }
                {
                    const int r1 = r0 + 8;
                    const int bb = r1 >> 10, ss = r1 & 1023;
                    *(__half2*)&Ch[(size_t)((bb * H_ + hh) * S_ + ss) * DK_ + dd] =
                        __floats2half2_rn(v10, v11);
                }
            } else if (EPI == 4) {
                __half* Ch = (__half*)C;
                const int hh = c0 >> 6, dd = c0 & 63;
                const int bb = r0 >> 10, ss = r0 & 1023;
                const size_t base = (size_t)((bb * H_ + hh) * DK_ + dd) * S_ + ss;
                Ch[base]           = __float2half_rn(v00);
                Ch[base + S_]      = __float2half_rn(v01);
                Ch[base + 8]       = __float2half_rn(v10);
                Ch[base + S_ + 8]  = __float2half_rn(v11);
            } else if (EPI == 5) {
                __half* Ch = (__half*)C;
                *(__half2*)&Ch[(size_t)r0 * N + c0]       = __floats2half2_rn(v00, v01);
                *(__half2*)&Ch[(size_t)(r0 + 8) * N + c0] = __floats2half2_rn(v10, v11);
            } else {
                float* Cf = (float*)C;
                *(float2*)&Cf[(size_t)r0 * N + c0]       = make_float2(v00, v01);
                *(float2*)&Cf[(size_t)(r0 + 8) * N + c0] = make_float2(v10, v11);
            }
        }
    }
}

// ---------------------------------------------------------------------------
// FP16 mma.sync GEMM, cp.async 2-stage pipeline.
//   C[M,N] = A[M,K] @ Bt[N,K]^T + bias
//   CTA 128x128, 128 threads (4 warps 2x2), warp tile 64x64, BK=64.
//   2 stages -> 73.7KB smem -> 3 CTAs/SM (3 warps/SMSP).
// ---------------------------------------------------------------------------
#define HST   72                     // halves per row
#define HSTGH (128 * HST)            // halves per stage = 9216
#define HSTGB (HSTGH * 2)            // 18432 bytes
#define GEMM_SMEM (4 * HSTGB)        // 73728 (2 stages x (A,B))

template <int EPI>
__device__ __forceinline__ void gemm_f16_body(
    const __half* __restrict__ A, const __half* __restrict__ Bt,
    const float* __restrict__ bias, void* __restrict__ C,
    int N, int K, int m0, int n0)
{
    extern __shared__ __half smh[];
    const uint32_t sbase = smem_u32(smh);

    const int tid  = threadIdx.x;
    const int warp = tid >> 5;
    const int lane = tid & 31;
    const int wm = (warp >> 1) * 64;
    const int wn = (warp & 1) * 64;
    const int lq = lane >> 2;
    const int tq = lane & 3;

    const int rr  = tid >> 3;            // 0..15
    const int cc8 = (tid & 7) * 8;       // halves, 0..56

    const __half* Ap = A  + (size_t)(m0 + rr) * K + cc8;
    const __half* Bp = Bt + (size_t)(n0 + rr) * K + cc8;
    const uint32_t dA = sbase + (uint32_t)(rr * HST + cc8) * 2;
    const uint32_t dB = dA + 2 * HSTGB;

    const int KIT = K >> 6;

    float acc[4][8][4];
#pragma unroll
    for (int mi = 0; mi < 4; mi++)
#pragma unroll
        for (int ni = 0; ni < 8; ni++)
#pragma unroll
            for (int j = 0; j < 4; j++) acc[mi][ni][j] = 0.0f;

    auto issue = [&](int it) {
        if (it < KIT) {
            const __half* a = Ap + it * 64;
            const __half* b = Bp + it * 64;
            const uint32_t off = (uint32_t)(it & 1) * HSTGB;
#pragma unroll
            for (int i = 0; i < 8; i++) {
                cp16(dA + off + (uint32_t)(i * 16 * HST) * 2, a + (size_t)(i * 16) * K);
                cp16(dB + off + (uint32_t)(i * 16 * HST) * 2, b + (size_t)(i * 16) * K);
            }
        }
        CP_COMMIT;
    };

    issue(0); issue(1);

    for (int it = 0; it < KIT; ++it) {
        CP_WAIT1;
        __syncthreads();
        const __half* As = smh + (it & 1) * HSTGH;
        const __half* Bs = As + 2 * HSTGH;

#pragma unroll
        for (int s = 0; s < 4; ++s) {     // 4 x k16
            uint32_t bf[8][2];
#pragma unroll
            for (int ni = 0; ni < 8; ni++) {
                const int bb = (wn + ni * 8 + lq) * HST + s * 16 + 2 * tq;
                bf[ni][0] = *(const uint32_t*)&Bs[bb];
                bf[ni][1] = *(const uint32_t*)&Bs[bb + 8];
            }
#pragma unroll
            for (int mi = 0; mi < 4; mi++) {
                const int ab = (wm + mi * 16 + lq) * HST + s * 16 + 2 * tq;
                const uint32_t a0 = *(const uint32_t*)&As[ab];
                const uint32_t a1 = *(const uint32_t*)&As[ab + 8 * HST];
                const uint32_t a2 = *(const uint32_t*)&As[ab + 8];
                const uint32_t a3 = *(const uint32_t*)&As[ab + 8 * HST + 8];
#pragma unroll
                for (int ni = 0; ni < 8; ni++)
                    mma16(acc[mi][ni], a0, a1, a2, a3, bf[ni][0], bf[ni][1]);
            }
        }
        __syncthreads();
        issue(it + 2);
    }

    epilogue<EPI>(acc, bias, C, N, m0, n0, wm, wn, lq, tq);
}

template <int EPI>
__global__ void __launch_bounds__(128, 3)
mma_gemm_h(const __half* __restrict__ A, const __half* __restrict__ Bt,
           const float* __restrict__ bias, void* __restrict__ C,
           int N, int K)
{
    gemm_f16_body<EPI>(A, Bt, bias, C, N, K, blockIdx.y * 128, blockIdx.x * 128);
}

// Fully-fused QKV projection: grid.x = 18 (6 tiles x 3 sections).
// Section 0 -> Q [B,H,S,dk], 1 -> K [B,H,S,dk], 2 -> V^T [B,H,dk,S].
__global__ void __launch_bounds__(128, 3)
mma_gemm_h_qkv(const __half* __restrict__ A, const __half* __restrict__ wqkvT,
               const float* __restrict__ bq, const float* __restrict__ bk,
               const float* __restrict__ bv,
               __half* __restrict__ oq, __half* __restrict__ ok,
               __half* __restrict__ ovt)
{
    const int z  = blockIdx.x / 6;
    const int n0 = (blockIdx.x % 6) * 128;
    const int m0 = blockIdx.y * 128;
    const __half* Bt = wqkvT + (size_t)z * D_ * D_;
    if (z == 0)      gemm_f16_body<3>(A, Bt, bq, oq,  D_, D_, m0, n0);
    else if (z == 1) gemm_f16_body<3>(A, Bt, bk, ok,  D_, D_, m0, n0);
    else             gemm_f16_body<4>(A, Bt, bv, ovt, D_, D_, m0, n0);
}

// ---------------------------------------------------------------------------
// FP16 tensor-core flash attention; output stored fp16 [B,S,D].
// Block = 128 threads (4 warps), each warp owns 16 query rows -> 64 q/CTA.
// ---------------------------------------------------------------------------
__global__ void __launch_bounds__(128)
flash_attn_f16(const __half* __restrict__ Q,
               const __half* __restrict__ K,
               const __half* __restrict__ Vt,
               const int* __restrict__ mask,
               __half* __restrict__ O)
{
    const int qt = blockIdx.x;
    const int h  = blockIdx.y;
    const int b  = blockIdx.z;
    const int tid  = threadIdx.x;
    const int warp = tid >> 5;
    const int lane = tid & 31;
    const int lq = lane >> 2;
    const int tq = lane & 3;
    const int bh = b * H_ + h;

    __shared__ __half Ks[128 * 72];
    __shared__ __half Vs[64 * 136];
    __shared__ int mk[128];

    {
        const __half* Qb = Q + (size_t)(bh * S_ + qt * 64) * DK_;
        const int r = tid >> 1, hf = tid & 1;
        const uint4* src = (const uint4*)(Qb + r * DK_ + hf * 32);
        uint4* dst = (uint4*)&Ks[r * 72 + hf * 32];
#pragma unroll
        for (int i = 0; i < 4; i++) dst[i] = src[i];
    }
    __syncthreads();
    uint32_t qa[4][4];
    {
        const int r0 = warp * 16 + lq;
#pragma unroll
        for (int ks = 0; ks < 4; ks++) {
            qa[ks][0] = *(const uint32_t*)&Ks[(r0    ) * 72 + ks * 16 + 2 * tq];
            qa[ks][1] = *(const uint32_t*)&Ks[(r0 + 8) * 72 + ks * 16 + 2 * tq];
            qa[ks][2] = *(const uint32_t*)&Ks[(r0    ) * 72 + ks * 16 + 8 + 2 * tq];
            qa[ks][3] = *(const uint32_t*)&Ks[(r0 + 8) * 72 + ks * 16 + 8 + 2 * tq];
        }
    }
    __syncthreads();

    float o[8][4];
#pragma unroll
    for (int t = 0; t < 8; t++)
#pragma unroll
        for (int j = 0; j < 4; j++) o[t][j] = 0.0f;
    float m0 = -1e30f, m1 = -1e30f, l0 = 0.0f, l1 = 0.0f;

    const __half* Kb = K  + (size_t)bh * S_ * DK_;
    const __half* Vb = Vt + (size_t)bh * DK_ * S_;

    for (int kt = 0; kt < 8; kt++) {
        {
            const uint4* src = (const uint4*)(Kb + (size_t)(kt * 128 + tid) * DK_);
            uint4* dst = (uint4*)&Ks[tid * 72];
#pragma unroll
            for (int i = 0; i < 8; i++) dst[i] = src[i];
        }
        {
            const int r = tid >> 1, hf = tid & 1;
            const uint4* src = (const uint4*)(Vb + (size_t)r * S_ + kt * 128 + hf * 64);
            uint4* dst = (uint4*)&Vs[r * 136 + hf * 64];
#pragma unroll
            for (int i = 0; i < 8; i++) dst[i] = src[i];
        }
        mk[tid] = mask[b * S_ + kt * 128 + tid];
        __syncthreads();

        float s[16][4];
#pragma unroll
        for (int nt = 0; nt < 16; nt++) {
            s[nt][0] = s[nt][1] = s[nt][2] = s[nt][3] = 0.0f;
#pragma unroll
            for (int ks = 0; ks < 4; ks++) {
                const uint32_t b0 = *(const uint32_t*)&Ks[(nt * 8 + lq) * 72 + ks * 16 + 2 * tq];
                const uint32_t b1 = *(const uint32_t*)&Ks[(nt * 8 + lq) * 72 + ks * 16 + 8 + 2 * tq];
                mma16(s[nt], qa[ks][0], qa[ks][1], qa[ks][2], qa[ks][3], b0, b1);
            }
        }

        float mx0 = -1e30f, mx1 = -1e30f;
#pragma unroll
        for (int nt = 0; nt < 16; nt++) {
            const int c = nt * 8 + 2 * tq;
            const bool k0 = mk[c] != 0, k1 = mk[c + 1] != 0;
            s[nt][0] = k0 ? s[nt][0] * 0.125f : -1e9f;
            s[nt][1] = k1 ? s[nt][1] * 0.125f : -1e9f;
            s[nt][2] = k0 ? s[nt][2] * 0.125f : -1e9f;
            s[nt][3] = k1 ? s[nt][3] * 0.125f : -1e9f;
            mx0 = fmaxf(mx0, fmaxf(s[nt][0], s[nt][1]));
            mx1 = fmaxf(mx1, fmaxf(s[nt][2], s[nt][3]));
        }
        mx0 = fmaxf(mx0, __shfl_xor_sync(0xffffffffu, mx0, 1));
        mx0 = fmaxf(mx0, __shfl_xor_sync(0xffffffffu, mx0, 2));
        mx1 = fmaxf(mx1, __shfl_xor_sync(0xffffffffu, mx1, 1));
        mx1 = fmaxf(mx1, __shfl_xor_sync(0xffffffffu, mx1, 2));

        const float nm0 = fmaxf(m0, mx0);
        const float nm1 = fmaxf(m1, mx1);
        const float al0 = __expf(m0 - nm0);
        const float al1 = __expf(m1 - nm1);
        m0 = nm0; m1 = nm1;

        float ps0 = 0.0f, ps1 = 0.0f;
#pragma unroll
        for (int nt = 0; nt < 16; nt++) {
            s[nt][0] = __expf(s[nt][0] - m0);
            s[nt][1] = __expf(s[nt][1] - m0);
            s[nt][2] = __expf(s[nt][2] - m1);
            s[nt][3] = __expf(s[nt][3] - m1);
            ps0 += s[nt][0] + s[nt][1];
            ps1 += s[nt][2] + s[nt][3];
        }
        ps0 += __shfl_xor_sync(0xffffffffu, ps0, 1);
        ps0 += __shfl_xor_sync(0xffffffffu, ps0, 2);
        ps1 += __shfl_xor_sync(0xffffffffu, ps1, 1);
        ps1 += __shfl_xor_sync(0xffffffffu, ps1, 2);
        l0 = l0 * al0 + ps0;
        l1 = l1 * al1 + ps1;

#pragma unroll
        for (int t = 0; t < 8; t++) {
            o[t][0] *= al0; o[t][1] *= al0;
            o[t][2] *= al1; o[t][3] *= al1;
        }

#pragma unroll
        for (int kc = 0; kc < 8; kc++) {
            const uint32_t a0 = pack_f16(s[2 * kc][0],     s[2 * kc][1]);
            const uint32_t a1 = pack_f16(s[2 * kc][2],     s[2 * kc][3]);
            const uint32_t a2 = pack_f16(s[2 * kc + 1][0], s[2 * kc + 1][1]);
            const uint32_t a3 = pack_f16(s[2 * kc + 1][2], s[2 * kc + 1][3]);
#pragma unroll
            for (int t = 0; t < 8; t++) {
                const uint32_t b0 = *(const uint32_t*)&Vs[(t * 8 + lq) * 136 + kc * 16 + 2 * tq];
                const uint32_t b1 = *(const uint32_t*)&Vs[(t * 8 + lq) * 136 + kc * 16 + 8 + 2 * tq];
                mma16(o[t], a0, a1, a2, a3, b0, b1);
            }
        }
        __syncthreads();
    }

    // fp16 output (feeds Wo fp16 GEMM)
    const float i0 = 1.0f / l0;
    const float i1 = 1.0f / l1;
    const int qr = qt * 64 + warp * 16 + lq;
    __half* O0 = O + (size_t)(b * S_ + qr) * D_ + h * DK_;
    __half* O1 = O0 + (size_t)8 * D_;
#pragma unroll
    for (int t = 0; t < 8; t++) {
        *(__half2*)(O0 + t * 8 + 2 * tq) = __floats2half2_rn(o[t][0] * i0, o[t][1] * i0);
        *(__half2*)(O1 + t * 8 + 2 * tq) = __floats2half2_rn(o[t][2] * i1, o[t][3] * i1);
    }
}

// ---------------------------------------------------------------------------
// Fused residual add + LayerNorm; optionally writes fp16 copy.
// ---------------------------------------------------------------------------
template <bool WH>
__global__ void __launch_bounds__(256)
ln_residual_kernel(const float* __restrict__ X, const float* __restrict__ R,
                   const float* __restrict__ ga, const float* __restrict__ gb,
                   float* __restrict__ out, __half* __restrict__ outh)
{
    const int row = blockIdx.x;
    const int t   = threadIdx.x;
    const float* xr = X + (size_t)row * D_;
    const float* rr = R + (size_t)row * D_;

    float v[3];
#pragma unroll
    for (int i = 0; i < 3; i++) v[i] = xr[t + i * 256] + rr[t + i * 256];

    __shared__ float sbuf[8];

    float s = v[0] + v[1] + v[2];
#pragma unroll
    for (int off = 16; off > 0; off >>= 1) s += __shfl_xor_sync(0xffffffffu, s, off);
    if ((t & 31) == 0) sbuf[t >> 5] = s;
    __syncthreads();
    float tot = 0.f;
#pragma unroll
    for (int i = 0; i < 8; i++) tot += sbuf[i];
    const float mean = tot * (1.0f / (float)D_);
    __syncthreads();

    float d0 = v[0] - mean, d1 = v[1] - mean, d2 = v[2] - mean;
    float sq = d0 * d0 + d1 * d1 + d2 * d2;
#pragma unroll
    for (int off = 16; off > 0; off >>= 1) sq += __shfl_xor_sync(0xffffffffu, sq, off);
    if ((t & 31) == 0) sbuf[t >> 5] = sq;
    __syncthreads();
    float tot2 = 0.f;
#pragma unroll
    for (int i = 0; i < 8; i++) tot2 += sbuf[i];
    const float var = tot2 * (1.0f / (float)(D_ - 1));
    const float inv = 1.0f / (sqrtf(var) + 1e-6f);

    float* orow = out + (size_t)row * D_;
    const float o0 = ga[t      ] * d0 * inv + gb[t      ];
    const float o1 = ga[t + 256] * d1 * inv + gb[t + 256];
    const float o2 = ga[t + 512] * d2 * inv + gb[t + 512];
    orow[t      ] = o0;
    orow[t + 256] = o1;
    orow[t + 512] = o2;
    if (WH) {
        __half* orh = outh + (size_t)row * D_;
        orh[t      ] = __float2half_rn(o0);
        orh[t + 256] = __float2half_rn(o1);
        orh[t + 512] = __float2half_rn(o2);
    }
}

// ---------------------------------------------------------------------------
// Launch
// ---------------------------------------------------------------------------
extern "C" void kernel_launch(void* const* d_in, const int* in_sizes, int n_in,
                              void* d_out, int out_size)
{
    const float* x    = (const float*)d_in[0];
    const int*   mask = (const int*)  d_in[1];
    const float* Wq   = (const float*)d_in[2];
    const float* bq   = (const float*)d_in[3];
    const float* Wk   = (const float*)d_in[4];
    const float* bk   = (const float*)d_in[5];
    const float* Wv   = (const float*)d_in[6];
    const float* bv   = (const float*)d_in[7];
    const float* Wo   = (const float*)d_in[8];
    const float* bo   = (const float*)d_in[9];
    const float* W1   = (const float*)d_in[10];
    const float* b1   = (const float*)d_in[11];
    const float* W2   = (const float*)d_in[12];
    const float* b2   = (const float*)d_in[13];
    const float* ln1a = (const float*)d_in[14];
    const float* ln1b = (const float*)d_in[15];
    const float* ln2a = (const float*)d_in[16];
    const float* ln2b = (const float*)d_in[17];

    __half *xh, *qh, *kh, *vth, *att, *ffh, *o1h;
    __half *wqkvT, *woT, *w1T, *w2T;
    float *tmp, *out1;
    cudaGetSymbolAddress((void**)&xh,    g_xh);
    cudaGetSymbolAddress((void**)&qh,    g_qh);
    cudaGetSymbolAddress((void**)&kh,    g_kh);
    cudaGetSymbolAddress((void**)&vth,   g_vth);
    cudaGetSymbolAddress((void**)&att,   g_att);
    cudaGetSymbolAddress((void**)&ffh,   g_ffh);
    cudaGetSymbolAddress((void**)&o1h,   g_o1h);
    cudaGetSymbolAddress((void**)&tmp,   g_tmp);
    cudaGetSymbolAddress((void**)&out1,  g_out1);
    cudaGetSymbolAddress((void**)&wqkvT, g_wqkvT);
    cudaGetSymbolAddress((void**)&woT,   g_woT);
    cudaGetSymbolAddress((void**)&w1T,   g_w1T);
    cudaGetSymbolAddress((void**)&w2T,   g_w2T);

    cudaFuncSetAttribute(mma_gemm_h<0>,  cudaFuncAttributeMaxDynamicSharedMemorySize, GEMM_SMEM);
    cudaFuncSetAttribute(mma_gemm_h<5>,  cudaFuncAttributeMaxDynamicSharedMemorySize, GEMM_SMEM);
    cudaFuncSetAttribute(mma_gemm_h_qkv, cudaFuncAttributeMaxDynamicSharedMemorySize, GEMM_SMEM);

    // x -> fp16
    round_xh_kernel<<<(M_ * D_) / 4 / 256, 256>>>((const float4*)x, (uint2*)xh);

    // Weight transposes (QKV concatenated into wqkvT)
    dim3 tb(32, 8);
    transpose_qkvo<<<dim3(D_ / 32, D_ / 32, 4), tb>>>(
        Wq, Wk, Wv, Wo,
        wqkvT, wqkvT + (size_t)D_ * D_, wqkvT + (size_t)2 * D_ * D_, woT);
    transpose_f16<<<dim3(D_ / 32, F_ / 32), tb>>>(W1, w1T, D_, F_);
    transpose_f16<<<dim3(F_ / 32, D_ / 32), tb>>>(W2, w2T, F_, D_);

    dim3 gProj(D_ / 128, M_ / 128);          // (6, 64)
    dim3 gQkv (3 * D_ / 128, M_ / 128);      // (18, 64)
    dim3 gFfn1(F_ / 128, M_ / 128);          // (24, 64)

    // Fused QKV projection
    mma_gemm_h_qkv<<<gQkv, 128, GEMM_SMEM>>>(xh, wqkvT, bq, bk, bv, qh, kh, vth);

    // Attention (fp16 tensor cores, fp16 output)
    dim3 gAttn(S_ / 64, H_, B_);
    flash_attn_f16<<<gAttn, 128>>>(qh, kh, vth, mask, att);

    // Output projection (fp16)
    mma_gemm_h<0><<<gProj, 128, GEMM_SMEM>>>(att, woT, bo, tmp, D_, D_);

    // LN1(x + attn_out) -> out1 (fp32) + o1h (fp16, FFN1 A-operand)
    ln_residual_kernel<true><<<M_, 256>>>(x, tmp, ln1a, ln1b, out1, o1h);

    // FFN1 (fp16, gelu -> fp16) ; FFN2 (fp16)
    mma_gemm_h<5><<<gFfn1, 128, GEMM_SMEM>>>(o1h, w1T, b1, ffh, F_, D_);
    mma_gemm_h<0><<<gProj, 128, GEMM_SMEM>>>(ffh, w2T, b2, tmp, D_, F_);

    // LN2(out1 + ffn) -> output
    ln_residual_kernel<false><<<M_, 256>>>(out1, tmp, ln2a, ln2b, (float*)d_out, nullptr);
}